// round 9
// baseline (speedup 1.0000x reference)
#include <cuda_runtime.h>
#include <cuda_fp16.h>
#include <math.h>
#include <stdint.h>

#define B_ROWS 2048
#define D_DIM  512
#define W_DIM  512
#define N_LEAF 64
#define N_NODE 63

// ---------------------------------------------------------------------------
// Device scratch (no cudaMalloc allowed)
// ---------------------------------------------------------------------------
__device__ float g_dist[B_ROWS * N_LEAF];
// Fragment-permuted fp16 T: per (l, nb64, kc) an 8KB tile of 256 fragment rows
// row r = (h*4 + ks)*32 + lane (h = 32-col half), 8 half2 words (32 B) each.
__device__ __half g_Tp[(size_t)N_LEAF * 8 * 8 * 4096];

// ---------------------------------------------------------------------------
// Helpers
// ---------------------------------------------------------------------------
__device__ __forceinline__ uint32_t smem_u32(const void* p) {
    uint32_t a;
    asm("{ .reg .u64 t; cvta.to.shared.u64 t, %1; cvt.u32.u64 %0, t; }"
        : "=r"(a) : "l"(p));
    return a;
}

// Bank-conflict-killing swizzle: flip bit 4 when bit 7 is set.
// Applied IDENTICALLY on cp.async write and on LDS.128 read granules.
__device__ __forceinline__ uint32_t swz(uint32_t a) {
    return a ^ (((a >> 7) & 1u) << 4);
}

__device__ __forceinline__ float sigmoidf_(float z) { return 1.0f / (1.0f + expf(-z)); }

__device__ __forceinline__ void mma_f16(float c[4], const uint32_t a[4], const uint32_t b[2]) {
    asm volatile("mma.sync.aligned.m16n8k16.row.col.f32.f16.f16.f32 "
                 "{%0,%1,%2,%3}, {%4,%5,%6,%7}, {%8,%9}, {%0,%1,%2,%3};"
                 : "+f"(c[0]), "+f"(c[1]), "+f"(c[2]), "+f"(c[3])
                 : "r"(a[0]), "r"(a[1]), "r"(a[2]), "r"(a[3]), "r"(b[0]), "r"(b[1]));
}

__device__ __forceinline__ uint32_t pack_h2(float a, float b) {
    __half2 t = __floats2half2_rn(a, b);
    return *reinterpret_cast<uint32_t*>(&t);
}

#define CP_ASYNC16(dst, src) \
    asm volatile("cp.async.cg.shared.global [%0], [%1], 16;" :: "r"(dst), "l"(src))
#define CP_COMMIT() asm volatile("cp.async.commit_group;" ::: "memory")
#define CP_WAIT1()  asm volatile("cp.async.wait_group 1;" ::: "memory")

// ---------------------------------------------------------------------------
// Kernel 0: T [l][k][n] fp32 -> fragment-permuted fp16 g_Tp.
// One block per (kc, nb64, l): 64k x 64n tile -> 256 fragment rows x 32 B.
// ---------------------------------------------------------------------------
__global__ void __launch_bounds__(256) convert_kernel(const float* __restrict__ T) {
    __shared__ float tile[64][65];          // [k][n]
    const int tid = threadIdx.x;
    const int kc = blockIdx.x;
    const int nb = blockIdx.y;
    const int l  = blockIdx.z;

    const float* tp = T + ((size_t)l * D_DIM + kc * 64) * W_DIM + nb * 64;
#pragma unroll
    for (int e = 0; e < 16; e++) {
        int id = tid + e * 256;
        int k = id >> 6, n = id & 63;
        tile[k][n] = tp[(size_t)k * W_DIM + n];
    }
    __syncthreads();

    __half* dst = g_Tp + (((size_t)l * 8 + nb) * 8 + kc) * 4096;
    const int r  = tid;
    const int h  = r >> 7, ks = (r >> 5) & 3, ln = r & 31;
    const int g = ln >> 2, tg = ln & 3;
    uint32_t w[8];
#pragma unroll
    for (int j = 0; j < 4; j++) {
        int n  = h * 32 + j * 8 + g;
        int k0 = ks * 16 + 2 * tg;
        w[2 * j]     = pack_h2(tile[k0][n],     tile[k0 + 1][n]);
        w[2 * j + 1] = pack_h2(tile[k0 + 8][n], tile[k0 + 9][n]);
    }
    uint32_t* d = reinterpret_cast<uint32_t*>(dst + (size_t)r * 16);
    *reinterpret_cast<uint4*>(d)     = make_uint4(w[0], w[1], w[2], w[3]);
    *reinterpret_cast<uint4*>(d + 4) = make_uint4(w[4], w[5], w[6], w[7]);
}

// ---------------------------------------------------------------------------
// Kernel 1: angles -> decisions -> leaf distribution.  One warp per row.
// ---------------------------------------------------------------------------
__global__ void __launch_bounds__(256) dist_kernel(
    const float* __restrict__ x, const float* __restrict__ ray,
    const float* __restrict__ w_i, const float* __restrict__ b_i,
    const float* __restrict__ a_i, const int* __restrict__ idx)
{
    __shared__ float sray[D_DIM];
    __shared__ float sdec[8][64];

    const int tid = threadIdx.x;
    for (int i = tid; i < D_DIM; i += 256) sray[i] = ray[i];
    __syncthreads();

    const int warp = tid >> 5;
    const int lane = tid & 31;
    const int row  = blockIdx.x * 8 + warp;

    const float* xr = x + (size_t)row * D_DIM;
    float dot = 0.f, ss = 0.f, rss = 0.f;
#pragma unroll
    for (int j = 0; j < 4; j++) {
        float4 xv = reinterpret_cast<const float4*>(xr)[lane + 32 * j];
        float4 rv = reinterpret_cast<const float4*>(sray)[lane + 32 * j];
        dot += xv.x * rv.x + xv.y * rv.y + xv.z * rv.z + xv.w * rv.w;
        ss  += xv.x * xv.x + xv.y * xv.y + xv.z * xv.z + xv.w * xv.w;
        rss += rv.x * rv.x + rv.y * rv.y + rv.z * rv.z + rv.w * rv.w;
    }
#pragma unroll
    for (int o = 16; o > 0; o >>= 1) {
        dot += __shfl_xor_sync(0xffffffffu, dot, o);
        ss  += __shfl_xor_sync(0xffffffffu, ss,  o);
        rss += __shfl_xor_sync(0xffffffffu, rss, o);
    }
    float xn = fmaxf(sqrtf(ss),  1e-8f);
    float rn = fmaxf(sqrtf(rss), 1e-8f);
    float c  = dot / (xn * rn);
    c = fminf(fmaxf(c, -1.0f), 1.0f);
    const float angle = acosf(c) * 0.3183098861837907f;

    for (int n = lane; n < N_NODE; n += 32) {
        float nf = (0.5f + sigmoidf_(w_i[n])) * angle - sigmoidf_(b_i[n]);
        sdec[warp][n] = sigmoidf_(nf * (1.0f + a_i[n]));
    }
    __syncwarp();

    for (int leaf = lane; leaf < N_LEAF; leaf += 32) {
        float p = 1.0f;
#pragma unroll
        for (int t = 0; t < 6; t++) {
            int j = idx[leaf * 6 + t];
            float v = (j < N_NODE) ? sdec[warp][j] : (1.0f - sdec[warp][j - N_NODE]);
            p *= v;
        }
        g_dist[row * N_LEAF + leaf] = p;
    }
}

// ---------------------------------------------------------------------------
// Kernel 2: fp16 warp-mma GEMM, 4 CTAs/SM, 3-stage cp.async pipeline.
// CTA: 64m x 32n, 128 threads = 4 warps (2m x 2n), warp tile 32x16.
// Flattened it = kc*64 + l over 512 B tiles; X rebuilt at l==0.
// ---------------------------------------------------------------------------
// smem bytes: X half2-words [64][36] @0 (9216) | B 3x4096 @9216 | Dt @21504
#define XWOFF  0
#define BOFF   9216
#define DTOFF  21504
#define SMEM_BYTES (21504 + 17408)

__device__ __forceinline__ void issue_b(uint32_t dstbase, int it, int nb64, int h, int tid) {
    const int kc = it >> 6, l = it & 63;
    const char* src = (const char*)(g_Tp + (((size_t)l * 8 + nb64) * 8 + kc) * 4096)
                      + h * 4096;
#pragma unroll
    for (int e = 0; e < 2; e++) {
        int id = tid + e * 128;                 // 0..255 16B granules (4KB)
        uint32_t off = (uint32_t)id * 16;
        CP_ASYNC16(dstbase + swz(off), src + off);
    }
}

__global__ void __launch_bounds__(128, 4) gemm_f16_kernel(
    const float* __restrict__ x, float* __restrict__ out)
{
    extern __shared__ char sm[];
    const uint32_t sb = smem_u32(sm);
    const int tid  = threadIdx.x;
    const int wid  = tid >> 5;
    const int lane = tid & 31;
    const int wm   = wid & 1;       // 2 m-warps (32 rows)
    const int wn   = wid >> 1;      // 2 n-warps (16 cols)
    const int g    = lane >> 2;
    const int tg   = lane & 3;
    const int m0 = blockIdx.y * 64;
    const int nb32 = blockIdx.x;          // 0..15
    const int nb64 = nb32 >> 1;
    const int h    = nb32 & 1;            // which 32-col half of the 64-tile
    const int n0 = nb32 * 32;

    uint32_t* XW = reinterpret_cast<uint32_t*>(sm + XWOFF);  // half2 words, pitch 36
    float*    Dt = reinterpret_cast<float*>(sm + DTOFF);     // pitch 68
    // lane granule: 16B slice (wn) of this lane's 32B fragment row
    const uint32_t lane_sw = swz((uint32_t)lane * 32 + (uint32_t)wn * 16);

    // Load distribution tile [64 x 64], pitch 68
#pragma unroll
    for (int e = 0; e < 8; e++) {
        int id = tid + e * 128;
        int r = id >> 4, q = id & 15;
        float4 v = reinterpret_cast<const float4*>(g_dist + (size_t)(m0 + r) * N_LEAF)[q];
        *reinterpret_cast<float4*>(Dt + r * 68 + q * 4) = v;
    }

    float O[2][2][4];
#pragma unroll
    for (int i = 0; i < 2; i++)
#pragma unroll
        for (int j = 0; j < 2; j++)
#pragma unroll
            for (int r = 0; r < 4; r++) O[i][j][r] = 0.f;

    // Prologue: prefetch B tiles for it=0 and it=1 into buffers 0, 1
    issue_b(sb + BOFF, 0, nb64, h, tid);
    CP_COMMIT();
    issue_b(sb + BOFF + 4096, 1, nb64, h, tid);
    CP_COMMIT();

    uint32_t A[4][2][4];

    for (int it = 0; it < 512; it++) {
        const int l = it & 63;

        CP_WAIT1();            // group 'it' landed (group it+1 may be in flight)
        __syncthreads();       // B buf[it%3] visible; buf[(it+2)%3] free

        if (l == 0) {
            // ---- rebuild X tile [64m x 64k] fp16 (half2 words, pitch 36) ----
            const float* xp = x + (size_t)m0 * D_DIM + (it >> 6) * 64;
#pragma unroll
            for (int e = 0; e < 8; e++) {
                int id = tid + e * 128;        // 0..1023 float4s (64 rows x 16)
                int m = id >> 4, q = id & 15;
                float4 v = *reinterpret_cast<const float4*>(xp + (size_t)m * D_DIM + q * 4);
                uint2 u = make_uint2(pack_h2(v.x, v.y), pack_h2(v.z, v.w));
                *reinterpret_cast<uint2*>(XW + m * 36 + q * 2) = u;
            }
            __syncthreads();
            // ---- A fragments into registers (held across the 64-leaf run) ----
#pragma unroll
            for (int ks = 0; ks < 4; ks++) {
#pragma unroll
                for (int i = 0; i < 2; i++) {
                    int m = wm * 32 + i * 16 + g;
                    int k = ks * 8 + tg;
                    A[ks][i][0] = XW[m * 36 + k];
                    A[ks][i][1] = XW[(m + 8) * 36 + k];
                    A[ks][i][2] = XW[m * 36 + k + 4];
                    A[ks][i][3] = XW[(m + 8) * 36 + k + 4];
                }
            }
        }

        // Prefetch B tile for it+2 into buffer (it+2)%3 (always commit)
        if (it + 2 < 512)
            issue_b(sb + BOFF + ((it + 2) % 3) * 4096, it + 2, nb64, h, tid);
        CP_COMMIT();

        const char* Bb = sm + BOFF + (it % 3) * 4096;

        float P[2][2][4];
#pragma unroll
        for (int i = 0; i < 2; i++)
#pragma unroll
            for (int j = 0; j < 2; j++)
#pragma unroll
                for (int r = 0; r < 4; r++) P[i][j][r] = 0.f;

        uint4 c0 = *reinterpret_cast<const uint4*>(Bb + lane_sw);
#pragma unroll
        for (int ks = 0; ks < 4; ks++) {
            uint4 n0_;
            if (ks < 3)
                n0_ = *reinterpret_cast<const uint4*>(Bb + (ks + 1) * 1024 + lane_sw);
            uint32_t b[2][2];
            b[0][0] = c0.x; b[0][1] = c0.y;
            b[1][0] = c0.z; b[1][1] = c0.w;
#pragma unroll
            for (int i = 0; i < 2; i++)
#pragma unroll
                for (int j = 0; j < 2; j++)
                    mma_f16(P[i][j], A[ks][i], b[j]);
            c0 = n0_;
        }

        // Epilogue: O += d[row, l] * P
#pragma unroll
        for (int i = 0; i < 2; i++) {
            int r0 = wm * 32 + i * 16 + g;
            float d0 = Dt[r0 * 68 + l];
            float d1 = Dt[(r0 + 8) * 68 + l];
#pragma unroll
            for (int j = 0; j < 2; j++) {
                O[i][j][0] = fmaf(d0, P[i][j][0], O[i][j][0]);
                O[i][j][1] = fmaf(d0, P[i][j][1], O[i][j][1]);
                O[i][j][2] = fmaf(d1, P[i][j][2], O[i][j][2]);
                O[i][j][3] = fmaf(d1, P[i][j][3], O[i][j][3]);
            }
        }
    }

    // Write output fragments
#pragma unroll
    for (int i = 0; i < 2; i++) {
        int r0 = m0 + wm * 32 + i * 16 + g;
#pragma unroll
        for (int j = 0; j < 2; j++) {
            int col = n0 + wn * 16 + j * 8 + 2 * tg;
            float2 v0 = make_float2(O[i][j][0], O[i][j][1]);
            float2 v1 = make_float2(O[i][j][2], O[i][j][3]);
            *reinterpret_cast<float2*>(out + (size_t)r0 * W_DIM + col)       = v0;
            *reinterpret_cast<float2*>(out + (size_t)(r0 + 8) * W_DIM + col) = v1;
        }
    }
}

// ---------------------------------------------------------------------------
extern "C" void kernel_launch(void* const* d_in, const int* in_sizes, int n_in,
                              void* d_out, int out_size)
{
    const float* x   = (const float*)d_in[0];
    const float* ray = (const float*)d_in[1];
    const float* w_i = (const float*)d_in[2];
    const float* b_i = (const float*)d_in[3];
    const float* a_i = (const float*)d_in[4];
    const float* T   = (const float*)d_in[5];
    const int*   idx = (const int*)d_in[6];
    float* out = (float*)d_out;

    cudaFuncSetAttribute(gemm_f16_kernel,
                         cudaFuncAttributeMaxDynamicSharedMemorySize, SMEM_BYTES);

    convert_kernel<<<dim3(8, 8, 64), 256>>>(T);
    dist_kernel<<<B_ROWS / 8, 256>>>(x, ray, w_i, b_i, a_i, idx);
    gemm_f16_kernel<<<dim3(W_DIM / 32, B_ROWS / 64), 128, SMEM_BYTES>>>(x, out);
}

// round 10
// speedup vs baseline: 1.0836x; 1.0836x over previous
#include <cuda_runtime.h>
#include <cuda_fp16.h>
#include <math.h>
#include <stdint.h>

#define B_ROWS 2048
#define D_DIM  512
#define W_DIM  512
#define N_LEAF 64
#define N_NODE 63

// ---------------------------------------------------------------------------
// Device scratch (no cudaMalloc allowed)
// ---------------------------------------------------------------------------
__device__ float g_dist[B_ROWS * N_LEAF];
// Fragment-permuted fp16 T: per (l, nb64, kc) an 8KB tile of 4 warp slices
// (16 cols each, contiguous 2KB). Granule row r = (w*4 + ks)*32 + lane, 16 B:
//   { pack(k0,k0+1 | n=w*16+g), pack(k0+8,k0+9 | n), pack(.. | n+8), pack(.. | n+8) }
__device__ __half g_Tp[(size_t)N_LEAF * 8 * 8 * 4096];

// ---------------------------------------------------------------------------
// Helpers
// ---------------------------------------------------------------------------
__device__ __forceinline__ uint32_t smem_u32(const void* p) {
    uint32_t a;
    asm("{ .reg .u64 t; cvta.to.shared.u64 t, %1; cvt.u32.u64 %0, t; }"
        : "=r"(a) : "l"(p));
    return a;
}

__device__ __forceinline__ float sigmoidf_(float z) { return 1.0f / (1.0f + expf(-z)); }

__device__ __forceinline__ void mma_f16(float c[4], const uint32_t a[4], const uint32_t b[2]) {
    asm volatile("mma.sync.aligned.m16n8k16.row.col.f32.f16.f16.f32 "
                 "{%0,%1,%2,%3}, {%4,%5,%6,%7}, {%8,%9}, {%0,%1,%2,%3};"
                 : "+f"(c[0]), "+f"(c[1]), "+f"(c[2]), "+f"(c[3])
                 : "r"(a[0]), "r"(a[1]), "r"(a[2]), "r"(a[3]), "r"(b[0]), "r"(b[1]));
}

__device__ __forceinline__ uint32_t pack_h2(float a, float b) {
    __half2 t = __floats2half2_rn(a, b);
    return *reinterpret_cast<uint32_t*>(&t);
}

#define CP_ASYNC16(dst, src) \
    asm volatile("cp.async.cg.shared.global [%0], [%1], 16;" :: "r"(dst), "l"(src))
#define CP_COMMIT() asm volatile("cp.async.commit_group;" ::: "memory")
#define CP_WAIT1()  asm volatile("cp.async.wait_group 1;" ::: "memory")

// ---------------------------------------------------------------------------
// Kernel 0: T [l][k][n] fp32 -> warp-sliced fragment-permuted fp16 g_Tp.
// One block per (kc, nb64, l): 64k x 64n tile -> 512 granule rows x 16 B.
// ---------------------------------------------------------------------------
__global__ void __launch_bounds__(256) convert_kernel(const float* __restrict__ T) {
    __shared__ float tile[64][65];          // [k][n]
    const int tid = threadIdx.x;
    const int kc = blockIdx.x;
    const int nb = blockIdx.y;
    const int l  = blockIdx.z;

    const float* tp = T + ((size_t)l * D_DIM + kc * 64) * W_DIM + nb * 64;
#pragma unroll
    for (int e = 0; e < 16; e++) {
        int id = tid + e * 256;
        int k = id >> 6, n = id & 63;
        tile[k][n] = tp[(size_t)k * W_DIM + n];
    }
    __syncthreads();

    char* dst = (char*)(g_Tp + (((size_t)l * 8 + nb) * 8 + kc) * 4096);
#pragma unroll
    for (int e = 0; e < 2; e++) {
        int r = tid + e * 256;               // 0..511 granule rows
        int w = r >> 7, ks = (r >> 5) & 3, ln = r & 31;
        int g = ln >> 2, tg = ln & 3;
        int k0 = ks * 16 + 2 * tg;
        int n0 = w * 16 + g;
        int n1 = n0 + 8;
        uint4 u;
        u.x = pack_h2(tile[k0][n0],     tile[k0 + 1][n0]);
        u.y = pack_h2(tile[k0 + 8][n0], tile[k0 + 9][n0]);
        u.z = pack_h2(tile[k0][n1],     tile[k0 + 1][n1]);
        u.w = pack_h2(tile[k0 + 8][n1], tile[k0 + 9][n1]);
        *reinterpret_cast<uint4*>(dst + (size_t)r * 16) = u;
    }
}

// ---------------------------------------------------------------------------
// Kernel 1: angles -> decisions -> leaf distribution.  One warp per row.
// ---------------------------------------------------------------------------
__global__ void __launch_bounds__(256) dist_kernel(
    const float* __restrict__ x, const float* __restrict__ ray,
    const float* __restrict__ w_i, const float* __restrict__ b_i,
    const float* __restrict__ a_i, const int* __restrict__ idx)
{
    __shared__ float sray[D_DIM];
    __shared__ float sdec[8][64];

    const int tid = threadIdx.x;
    for (int i = tid; i < D_DIM; i += 256) sray[i] = ray[i];
    __syncthreads();

    const int warp = tid >> 5;
    const int lane = tid & 31;
    const int row  = blockIdx.x * 8 + warp;

    const float* xr = x + (size_t)row * D_DIM;
    float dot = 0.f, ss = 0.f, rss = 0.f;
#pragma unroll
    for (int j = 0; j < 4; j++) {
        float4 xv = reinterpret_cast<const float4*>(xr)[lane + 32 * j];
        float4 rv = reinterpret_cast<const float4*>(sray)[lane + 32 * j];
        dot += xv.x * rv.x + xv.y * rv.y + xv.z * rv.z + xv.w * rv.w;
        ss  += xv.x * xv.x + xv.y * xv.y + xv.z * xv.z + xv.w * xv.w;
        rss += rv.x * rv.x + rv.y * rv.y + rv.z * rv.z + rv.w * rv.w;
    }
#pragma unroll
    for (int o = 16; o > 0; o >>= 1) {
        dot += __shfl_xor_sync(0xffffffffu, dot, o);
        ss  += __shfl_xor_sync(0xffffffffu, ss,  o);
        rss += __shfl_xor_sync(0xffffffffu, rss, o);
    }
    float xn = fmaxf(sqrtf(ss),  1e-8f);
    float rn = fmaxf(sqrtf(rss), 1e-8f);
    float c  = dot / (xn * rn);
    c = fminf(fmaxf(c, -1.0f), 1.0f);
    const float angle = acosf(c) * 0.3183098861837907f;

    for (int n = lane; n < N_NODE; n += 32) {
        float nf = (0.5f + sigmoidf_(w_i[n])) * angle - sigmoidf_(b_i[n]);
        sdec[warp][n] = sigmoidf_(nf * (1.0f + a_i[n]));
    }
    __syncwarp();

    for (int leaf = lane; leaf < N_LEAF; leaf += 32) {
        float p = 1.0f;
#pragma unroll
        for (int t = 0; t < 6; t++) {
            int j = idx[leaf * 6 + t];
            float v = (j < N_NODE) ? sdec[warp][j] : (1.0f - sdec[warp][j - N_NODE]);
            p *= v;
        }
        g_dist[row * N_LEAF + leaf] = p;
    }
}

// ---------------------------------------------------------------------------
// Kernel 2: fp16 warp-mma GEMM, per-warp private B pipelines (NO per-iter
// __syncthreads). CTA: 64m x 64n, 128 threads = 4 warps side-by-side in n
// (warp tile 64m x 16n). Each warp triple-buffers its own contiguous 2KB
// B slice via its own cp.async groups; visibility = wait_group + __syncwarp.
// CTA barriers only at kc boundaries (X tile rebuild): 16 total.
// ---------------------------------------------------------------------------
// smem bytes: X half2-words [64][36] @0 (9216) | B 4 warps x 3 x 2048 @9216 |
//             Dt [64][68] @33792 (17408)  -> total 51200
#define XWOFF  0
#define BOFF   9216
#define DTOFF  33792
#define SMEM_BYTES 51200

// Per-warp B slice prefetch: lane loads 4 x 16B granules (one per ks).
__device__ __forceinline__ void issue_bw(uint32_t dst, int it, int nb64,
                                         int wid, int lane) {
    const int kc = it >> 6, l = it & 63;
    const char* src = (const char*)(g_Tp + (((size_t)l * 8 + nb64) * 8 + kc) * 4096)
                      + wid * 2048 + lane * 16;
    uint32_t d = dst + lane * 16;
#pragma unroll
    for (int ks = 0; ks < 4; ks++)
        CP_ASYNC16(d + ks * 512, src + ks * 512);
}

__global__ void __launch_bounds__(128, 2) gemm_f16_kernel(
    const float* __restrict__ x, float* __restrict__ out)
{
    extern __shared__ char sm[];
    const uint32_t sb = smem_u32(sm);
    const int tid  = threadIdx.x;
    const int wid  = tid >> 5;      // warp = n-slice owner (16 cols)
    const int lane = tid & 31;
    const int g    = lane >> 2;
    const int tg   = lane & 3;
    const int m0 = blockIdx.y * 64;
    const int nb64 = blockIdx.x;
    const int n0 = nb64 * 64;

    uint32_t* XW = reinterpret_cast<uint32_t*>(sm + XWOFF);  // half2 words, pitch 36
    float*    Dt = reinterpret_cast<float*>(sm + DTOFF);     // pitch 68
    const uint32_t wbase = sb + BOFF + wid * 6144;           // this warp's 3 buffers

    // Load distribution tile [64 x 64], pitch 68 (visible after first barrier)
#pragma unroll
    for (int e = 0; e < 8; e++) {
        int id = tid + e * 128;
        int r = id >> 4, q = id & 15;
        float4 v = reinterpret_cast<const float4*>(g_dist + (size_t)(m0 + r) * N_LEAF)[q];
        *reinterpret_cast<float4*>(Dt + r * 68 + q * 4) = v;
    }

    float O[4][2][4];
#pragma unroll
    for (int i = 0; i < 4; i++)
#pragma unroll
        for (int j = 0; j < 2; j++)
#pragma unroll
            for (int r = 0; r < 4; r++) O[i][j][r] = 0.f;

    // Prologue: per-warp prefetch of it=0, it=1 into buffers 0, 1
    issue_bw(wbase, 0, nb64, wid, lane);
    CP_COMMIT();
    issue_bw(wbase + 2048, 1, nb64, wid, lane);
    CP_COMMIT();

    uint32_t A[4][4][4];   // [ks][m16 tile][regs]

    for (int it = 0; it < 512; it++) {
        const int l = it & 63;

        if (l == 0) {
            // ---- CTA-wide X tile rebuild (only 8 times) ----
            __syncthreads();   // all warps done reading X (A-frag loads)
            const float* xp = x + (size_t)m0 * D_DIM + (it >> 6) * 64;
#pragma unroll
            for (int e = 0; e < 8; e++) {
                int id = tid + e * 128;        // 0..1023 float4s (64 rows x 16)
                int m = id >> 4, q = id & 15;
                float4 v = *reinterpret_cast<const float4*>(xp + (size_t)m * D_DIM + q * 4);
                uint2 u = make_uint2(pack_h2(v.x, v.y), pack_h2(v.z, v.w));
                *reinterpret_cast<uint2*>(XW + m * 36 + q * 2) = u;
            }
            __syncthreads();
            // ---- A fragments into registers (held across the 64-leaf run) ----
#pragma unroll
            for (int ks = 0; ks < 4; ks++) {
#pragma unroll
                for (int i = 0; i < 4; i++) {
                    int m = i * 16 + g;
                    int k = ks * 8 + tg;
                    A[ks][i][0] = XW[m * 36 + k];
                    A[ks][i][1] = XW[(m + 8) * 36 + k];
                    A[ks][i][2] = XW[m * 36 + k + 4];
                    A[ks][i][3] = XW[(m + 8) * 36 + k + 4];
                }
            }
        }

        // ---- per-warp pipeline: group 'it' landed; issue it+2 ----
        CP_WAIT1();
        __syncwarp();
        if (it + 2 < 512)
            issue_bw(wbase + ((it + 2) % 3) * 2048, it + 2, nb64, wid, lane);
        CP_COMMIT();

        const uint32_t bb = wbase + (it % 3) * 2048 + lane * 16;

        float P[4][2][4];
#pragma unroll
        for (int i = 0; i < 4; i++)
#pragma unroll
            for (int j = 0; j < 2; j++)
#pragma unroll
                for (int r = 0; r < 4; r++) P[i][j][r] = 0.f;

#pragma unroll
        for (int ks = 0; ks < 4; ks++) {
            uint4 c = *reinterpret_cast<const uint4*>(
                reinterpret_cast<const char*>(sm) + (bb - sb) + ks * 512);
            uint32_t b[2][2];
            b[0][0] = c.x; b[0][1] = c.y;
            b[1][0] = c.z; b[1][1] = c.w;
#pragma unroll
            for (int i = 0; i < 4; i++)
#pragma unroll
                for (int j = 0; j < 2; j++)
                    mma_f16(P[i][j], A[ks][i], b[j]);
        }

        // Epilogue: O += d[row, l] * P
#pragma unroll
        for (int i = 0; i < 4; i++) {
            int r0 = i * 16 + g;
            float d0 = Dt[r0 * 68 + l];
            float d1 = Dt[(r0 + 8) * 68 + l];
#pragma unroll
            for (int j = 0; j < 2; j++) {
                O[i][j][0] = fmaf(d0, P[i][j][0], O[i][j][0]);
                O[i][j][1] = fmaf(d0, P[i][j][1], O[i][j][1]);
                O[i][j][2] = fmaf(d1, P[i][j][2], O[i][j][2]);
                O[i][j][3] = fmaf(d1, P[i][j][3], O[i][j][3]);
            }
        }
    }

    // Write output fragments
#pragma unroll
    for (int i = 0; i < 4; i++) {
        int r0 = m0 + i * 16 + g;
#pragma unroll
        for (int j = 0; j < 2; j++) {
            int col = n0 + wid * 16 + j * 8 + 2 * tg;
            float2 v0 = make_float2(O[i][j][0], O[i][j][1]);
            float2 v1 = make_float2(O[i][j][2], O[i][j][3]);
            *reinterpret_cast<float2*>(out + (size_t)r0 * W_DIM + col)       = v0;
            *reinterpret_cast<float2*>(out + (size_t)(r0 + 8) * W_DIM + col) = v1;
        }
    }
}

// ---------------------------------------------------------------------------
extern "C" void kernel_launch(void* const* d_in, const int* in_sizes, int n_in,
                              void* d_out, int out_size)
{
    const float* x   = (const float*)d_in[0];
    const float* ray = (const float*)d_in[1];
    const float* w_i = (const float*)d_in[2];
    const float* b_i = (const float*)d_in[3];
    const float* a_i = (const float*)d_in[4];
    const float* T   = (const float*)d_in[5];
    const int*   idx = (const int*)d_in[6];
    float* out = (float*)d_out;

    cudaFuncSetAttribute(gemm_f16_kernel,
                         cudaFuncAttributeMaxDynamicSharedMemorySize, SMEM_BYTES);

    convert_kernel<<<dim3(8, 8, 64), 256>>>(T);
    dist_kernel<<<B_ROWS / 8, 256>>>(x, ray, w_i, b_i, a_i, idx);
    gemm_f16_kernel<<<dim3(W_DIM / 64, B_ROWS / 64), 128, SMEM_BYTES>>>(x, out);
}

// round 11
// speedup vs baseline: 1.2471x; 1.1508x over previous
#include <cuda_runtime.h>
#include <cuda_fp16.h>
#include <math.h>
#include <stdint.h>

#define B_ROWS 2048
#define D_DIM  512
#define W_DIM  512
#define N_LEAF 64
#define N_NODE 63

// ---------------------------------------------------------------------------
// Device scratch (no cudaMalloc allowed)
// ---------------------------------------------------------------------------
__device__ float g_dist[B_ROWS * N_LEAF];
// Fragment-permuted fp16 T: per (l, nb64, kc64) an 8KB tile of 4 warp slices
// (16 cols each, contiguous 2KB). Granule row r = (w*4 + ks)*32 + lane, 16 B.
__device__ __half g_Tp[(size_t)N_LEAF * 8 * 8 * 4096];

// ---------------------------------------------------------------------------
// Helpers
// ---------------------------------------------------------------------------
__device__ __forceinline__ uint32_t smem_u32(const void* p) {
    uint32_t a;
    asm("{ .reg .u64 t; cvta.to.shared.u64 t, %1; cvt.u32.u64 %0, t; }"
        : "=r"(a) : "l"(p));
    return a;
}

__device__ __forceinline__ float sigmoidf_(float z) { return 1.0f / (1.0f + expf(-z)); }

__device__ __forceinline__ void mma_f16(float c[4], const uint32_t a[4], const uint32_t b[2]) {
    asm volatile("mma.sync.aligned.m16n8k16.row.col.f32.f16.f16.f32 "
                 "{%0,%1,%2,%3}, {%4,%5,%6,%7}, {%8,%9}, {%0,%1,%2,%3};"
                 : "+f"(c[0]), "+f"(c[1]), "+f"(c[2]), "+f"(c[3])
                 : "r"(a[0]), "r"(a[1]), "r"(a[2]), "r"(a[3]), "r"(b[0]), "r"(b[1]));
}

__device__ __forceinline__ uint32_t pack_h2(float a, float b) {
    __half2 t = __floats2half2_rn(a, b);
    return *reinterpret_cast<uint32_t*>(&t);
}

#define CP_ASYNC16(dst, src) \
    asm volatile("cp.async.cg.shared.global [%0], [%1], 16;" :: "r"(dst), "l"(src))
#define CP_COMMIT() asm volatile("cp.async.commit_group;" ::: "memory")
#define CP_WAIT1()  asm volatile("cp.async.wait_group 1;" ::: "memory")

// ---------------------------------------------------------------------------
// Kernel 0: T [l][k][n] fp32 -> warp-sliced fragment-permuted fp16 g_Tp.
// One block per (kc64, nb64, l): 64k x 64n tile -> 512 granule rows x 16 B.
// ---------------------------------------------------------------------------
__global__ void __launch_bounds__(256) convert_kernel(const float* __restrict__ T) {
    __shared__ float tile[64][65];          // [k][n]
    const int tid = threadIdx.x;
    const int kc = blockIdx.x;
    const int nb = blockIdx.y;
    const int l  = blockIdx.z;

    const float* tp = T + ((size_t)l * D_DIM + kc * 64) * W_DIM + nb * 64;
#pragma unroll
    for (int e = 0; e < 16; e++) {
        int id = tid + e * 256;
        int k = id >> 6, n = id & 63;
        tile[k][n] = tp[(size_t)k * W_DIM + n];
    }
    __syncthreads();

    char* dst = (char*)(g_Tp + (((size_t)l * 8 + nb) * 8 + kc) * 4096);
#pragma unroll
    for (int e = 0; e < 2; e++) {
        int r = tid + e * 256;               // 0..511 granule rows
        int w = r >> 7, ks = (r >> 5) & 3, ln = r & 31;
        int g = ln >> 2, tg = ln & 3;
        int k0 = ks * 16 + 2 * tg;
        int n0 = w * 16 + g;
        int n1 = n0 + 8;
        uint4 u;
        u.x = pack_h2(tile[k0][n0],     tile[k0 + 1][n0]);
        u.y = pack_h2(tile[k0 + 8][n0], tile[k0 + 9][n0]);
        u.z = pack_h2(tile[k0][n1],     tile[k0 + 1][n1]);
        u.w = pack_h2(tile[k0 + 8][n1], tile[k0 + 9][n1]);
        *reinterpret_cast<uint4*>(dst + (size_t)r * 16) = u;
    }
}

// ---------------------------------------------------------------------------
// Kernel 1: angles -> decisions -> leaf distribution.  One warp per row.
// ---------------------------------------------------------------------------
__global__ void __launch_bounds__(256) dist_kernel(
    const float* __restrict__ x, const float* __restrict__ ray,
    const float* __restrict__ w_i, const float* __restrict__ b_i,
    const float* __restrict__ a_i, const int* __restrict__ idx)
{
    __shared__ float sray[D_DIM];
    __shared__ float sdec[8][64];

    const int tid = threadIdx.x;
    for (int i = tid; i < D_DIM; i += 256) sray[i] = ray[i];
    __syncthreads();

    const int warp = tid >> 5;
    const int lane = tid & 31;
    const int row  = blockIdx.x * 8 + warp;

    const float* xr = x + (size_t)row * D_DIM;
    float dot = 0.f, ss = 0.f, rss = 0.f;
#pragma unroll
    for (int j = 0; j < 4; j++) {
        float4 xv = reinterpret_cast<const float4*>(xr)[lane + 32 * j];
        float4 rv = reinterpret_cast<const float4*>(sray)[lane + 32 * j];
        dot += xv.x * rv.x + xv.y * rv.y + xv.z * rv.z + xv.w * rv.w;
        ss  += xv.x * xv.x + xv.y * xv.y + xv.z * xv.z + xv.w * xv.w;
        rss += rv.x * rv.x + rv.y * rv.y + rv.z * rv.z + rv.w * rv.w;
    }
#pragma unroll
    for (int o = 16; o > 0; o >>= 1) {
        dot += __shfl_xor_sync(0xffffffffu, dot, o);
        ss  += __shfl_xor_sync(0xffffffffu, ss,  o);
        rss += __shfl_xor_sync(0xffffffffu, rss, o);
    }
    float xn = fmaxf(sqrtf(ss),  1e-8f);
    float rn = fmaxf(sqrtf(rss), 1e-8f);
    float c  = dot / (xn * rn);
    c = fminf(fmaxf(c, -1.0f), 1.0f);
    const float angle = acosf(c) * 0.3183098861837907f;

    for (int n = lane; n < N_NODE; n += 32) {
        float nf = (0.5f + sigmoidf_(w_i[n])) * angle - sigmoidf_(b_i[n]);
        sdec[warp][n] = sigmoidf_(nf * (1.0f + a_i[n]));
    }
    __syncwarp();

    for (int leaf = lane; leaf < N_LEAF; leaf += 32) {
        float p = 1.0f;
#pragma unroll
        for (int t = 0; t < 6; t++) {
            int j = idx[leaf * 6 + t];
            float v = (j < N_NODE) ? sdec[warp][j] : (1.0f - sdec[warp][j - N_NODE]);
            p *= v;
        }
        g_dist[row * N_LEAF + leaf] = p;
    }
}

// ---------------------------------------------------------------------------
// Kernel 2: fp16 warp-mma GEMM, kc=128 register-resident A, per-warp private
// B pipelines. CTA: 64m x 64n, 128 threads = 4 warps side-by-side in n
// (warp tile 64m x 16n). it = chunk*64 + l over 256 iterations (4 chunks of
// 128 k). Per warp-iter: 8 LDS.128 (B) + 64 HMMA + 32-FFMA epilogue.
// Visibility of B = per-warp wait_group + __syncwarp; CTA barriers only at
// chunk boundaries (8 total).
// ---------------------------------------------------------------------------
// smem bytes: X half2-words [64][68] @0 (17408) | B 4w x 3 x 4096 @17408 |
//             Dt [64][68] fp32 @66560 (17408)  -> total 83968
#define XWOFF  0
#define BOFF   17408
#define DTOFF  66560
#define SMEM_BYTES 83968

// Per-warp B slice prefetch for a 128k chunk: two consecutive kc64 tiles,
// 8 x 16B granules per lane.
__device__ __forceinline__ void issue_bw(uint32_t dst, int it, int nb64,
                                         int wid, int lane) {
    const int chunk = it >> 6, l = it & 63;
    const char* src = (const char*)(g_Tp + (((size_t)l * 8 + nb64) * 8 + chunk * 2) * 4096)
                      + wid * 2048 + lane * 16;
    uint32_t d = dst + lane * 16;
#pragma unroll
    for (int gq = 0; gq < 8; gq++) {
        int s = gq >> 2, k4 = gq & 3;        // tile half, ks within tile
        CP_ASYNC16(d + gq * 512, src + s * 8192 + k4 * 512);
    }
}

__global__ void __launch_bounds__(128, 2) gemm_f16_kernel(
    const float* __restrict__ x, float* __restrict__ out)
{
    extern __shared__ char sm[];
    const uint32_t sb = smem_u32(sm);
    const int tid  = threadIdx.x;
    const int wid  = tid >> 5;      // warp = n-slice owner (16 cols)
    const int lane = tid & 31;
    const int g    = lane >> 2;
    const int tg   = lane & 3;
    const int m0 = blockIdx.y * 64;
    const int nb64 = blockIdx.x;
    const int n0 = nb64 * 64;

    uint32_t* XW = reinterpret_cast<uint32_t*>(sm + XWOFF);  // half2 words, pitch 68
    float*    Dt = reinterpret_cast<float*>(sm + DTOFF);     // pitch 68
    const uint32_t wbase = sb + BOFF + wid * 12288;          // this warp's 3 buffers

    // Load distribution tile [64 x 64], pitch 68 (visible after first barrier)
#pragma unroll
    for (int e = 0; e < 8; e++) {
        int id = tid + e * 128;
        int r = id >> 4, q = id & 15;
        float4 v = reinterpret_cast<const float4*>(g_dist + (size_t)(m0 + r) * N_LEAF)[q];
        *reinterpret_cast<float4*>(Dt + r * 68 + q * 4) = v;
    }

    float O[4][2][4];
#pragma unroll
    for (int i = 0; i < 4; i++)
#pragma unroll
        for (int j = 0; j < 2; j++)
#pragma unroll
            for (int r = 0; r < 4; r++) O[i][j][r] = 0.f;

    // Prologue: per-warp prefetch of it=0, it=1 into buffers 0, 1
    issue_bw(wbase, 0, nb64, wid, lane);
    CP_COMMIT();
    issue_bw(wbase + 4096, 1, nb64, wid, lane);
    CP_COMMIT();

    uint32_t A[8][4][4];   // [ks][m16 tile][regs] for the 128k chunk

    for (int it = 0; it < 256; it++) {
        const int l = it & 63;

        if (l == 0) {
            // ---- CTA-wide X tile rebuild [64m x 128k] (4 times total) ----
            __syncthreads();   // all warps done reading X (A-frag loads)
            const float* xp = x + (size_t)m0 * D_DIM + (it >> 6) * 128;
#pragma unroll
            for (int e = 0; e < 16; e++) {
                int id = tid + e * 128;        // 0..2047 float4s (64 rows x 32)
                int m = id >> 5, q = id & 31;
                float4 v = *reinterpret_cast<const float4*>(xp + (size_t)m * D_DIM + q * 4);
                uint2 u = make_uint2(pack_h2(v.x, v.y), pack_h2(v.z, v.w));
                *reinterpret_cast<uint2*>(XW + m * 68 + q * 2) = u;
            }
            __syncthreads();
            // ---- A fragments into registers (held across the 64-leaf run) ----
#pragma unroll
            for (int ks = 0; ks < 8; ks++) {
#pragma unroll
                for (int i = 0; i < 4; i++) {
                    int m = i * 16 + g;
                    int k = ks * 8 + tg;
                    A[ks][i][0] = XW[m * 68 + k];
                    A[ks][i][1] = XW[(m + 8) * 68 + k];
                    A[ks][i][2] = XW[m * 68 + k + 4];
                    A[ks][i][3] = XW[(m + 8) * 68 + k + 4];
                }
            }
        }

        // ---- per-warp pipeline: group 'it' landed; issue it+2 ----
        CP_WAIT1();
        __syncwarp();
        if (it + 2 < 256)
            issue_bw(wbase + ((it + 2) % 3) * 4096, it + 2, nb64, wid, lane);
        CP_COMMIT();

        const char* Bb = sm + (wbase - sb) + (it % 3) * 4096 + lane * 16;

        float P[4][2][4];
#pragma unroll
        for (int i = 0; i < 4; i++)
#pragma unroll
            for (int j = 0; j < 2; j++)
#pragma unroll
                for (int r = 0; r < 4; r++) P[i][j][r] = 0.f;

#pragma unroll
        for (int ks = 0; ks < 8; ks++) {
            uint4 c = *reinterpret_cast<const uint4*>(Bb + ks * 512);
            uint32_t b[2][2];
            b[0][0] = c.x; b[0][1] = c.y;
            b[1][0] = c.z; b[1][1] = c.w;
#pragma unroll
            for (int i = 0; i < 4; i++)
#pragma unroll
                for (int j = 0; j < 2; j++)
                    mma_f16(P[i][j], A[ks][i], b[j]);
        }

        // Epilogue: O += d[row, l] * P
#pragma unroll
        for (int i = 0; i < 4; i++) {
            int r0 = i * 16 + g;
            float d0 = Dt[r0 * 68 + l];
            float d1 = Dt[(r0 + 8) * 68 + l];
#pragma unroll
            for (int j = 0; j < 2; j++) {
                O[i][j][0] = fmaf(d0, P[i][j][0], O[i][j][0]);
                O[i][j][1] = fmaf(d0, P[i][j][1], O[i][j][1]);
                O[i][j][2] = fmaf(d1, P[i][j][2], O[i][j][2]);
                O[i][j][3] = fmaf(d1, P[i][j][3], O[i][j][3]);
            }
        }
    }

    // Write output fragments
#pragma unroll
    for (int i = 0; i < 4; i++) {
        int r0 = m0 + i * 16 + g;
#pragma unroll
        for (int j = 0; j < 2; j++) {
            int col = n0 + wid * 16 + j * 8 + 2 * tg;
            float2 v0 = make_float2(O[i][j][0], O[i][j][1]);
            float2 v1 = make_float2(O[i][j][2], O[i][j][3]);
            *reinterpret_cast<float2*>(out + (size_t)r0 * W_DIM + col)       = v0;
            *reinterpret_cast<float2*>(out + (size_t)(r0 + 8) * W_DIM + col) = v1;
        }
    }
}

// ---------------------------------------------------------------------------
extern "C" void kernel_launch(void* const* d_in, const int* in_sizes, int n_in,
                              void* d_out, int out_size)
{
    const float* x   = (const float*)d_in[0];
    const float* ray = (const float*)d_in[1];
    const float* w_i = (const float*)d_in[2];
    const float* b_i = (const float*)d_in[3];
    const float* a_i = (const float*)d_in[4];
    const float* T   = (const float*)d_in[5];
    const int*   idx = (const int*)d_in[6];
    float* out = (float*)d_out;

    cudaFuncSetAttribute(gemm_f16_kernel,
                         cudaFuncAttributeMaxDynamicSharedMemorySize, SMEM_BYTES);

    convert_kernel<<<dim3(8, 8, 64), 256>>>(T);
    dist_kernel<<<B_ROWS / 8, 256>>>(x, ray, w_i, b_i, a_i, idx);
    gemm_f16_kernel<<<dim3(W_DIM / 64, B_ROWS / 64), 128, SMEM_BYTES>>>(x, out);
}

// round 12
// speedup vs baseline: 2.1532x; 1.7266x over previous
#include <cuda_runtime.h>
#include <cuda_fp16.h>
#include <math.h>
#include <stdint.h>

#define B_ROWS 2048
#define D_DIM  512
#define W_DIM  512
#define N_LEAF 64
#define N_NODE 63
#define P_N    12
#define K_TOT  (P_N * D_DIM)     // 6144
#define N_KT   (K_TOT / 64)      // 96 kc64 tiles
#define N_CHUNK (K_TOT / 128)    // 48 kc128 chunks

// ---------------------------------------------------------------------------
// Device scratch (no cudaMalloc allowed)
// ---------------------------------------------------------------------------
__device__ float  g_theta[B_ROWS];
__device__ int    g_tmin_i, g_tmax_i;
__device__ float  g_Dn[P_N * N_LEAF];                       // d_l at nodes
__device__ __half g_A [(size_t)(B_ROWS / 64) * N_KT * 4096]; // A granules
__device__ __half g_Ut[(size_t)K_TOT * W_DIM];               // U row-major
__device__ __half g_Up[(size_t)(W_DIM / 64) * N_KT * 4096];  // U granules

// Chebyshev-1 nodes on [-1,1] and barycentric weights (canonical)
__device__ __constant__ float c_tp[12] = {
    0.9914448614f,  0.9238795325f,  0.7933533403f,  0.6087614290f,
    0.3826834324f,  0.1305261922f, -0.1305261922f, -0.3826834324f,
   -0.6087614290f, -0.7933533403f, -0.9238795325f, -0.9914448614f };
__device__ __constant__ float c_wp[12] = {
    0.1305261922f, -0.3826834324f,  0.6087614290f, -0.7933533403f,
    0.9238795325f, -0.9914448614f,  0.9914448614f, -0.9238795325f,
    0.7933533403f, -0.6087614290f,  0.3826834324f, -0.1305261922f };

// ---------------------------------------------------------------------------
// Helpers
// ---------------------------------------------------------------------------
__device__ __forceinline__ uint32_t smem_u32(const void* p) {
    uint32_t a;
    asm("{ .reg .u64 t; cvta.to.shared.u64 t, %1; cvt.u32.u64 %0, t; }"
        : "=r"(a) : "l"(p));
    return a;
}

__device__ __forceinline__ float sigmoidf_(float z) { return 1.0f / (1.0f + expf(-z)); }

__device__ __forceinline__ void mma_f16(float c[4], const uint32_t a[4], const uint32_t b[2]) {
    asm volatile("mma.sync.aligned.m16n8k16.row.col.f32.f16.f16.f32 "
                 "{%0,%1,%2,%3}, {%4,%5,%6,%7}, {%8,%9}, {%0,%1,%2,%3};"
                 : "+f"(c[0]), "+f"(c[1]), "+f"(c[2]), "+f"(c[3])
                 : "r"(a[0]), "r"(a[1]), "r"(a[2]), "r"(a[3]), "r"(b[0]), "r"(b[1]));
}

__device__ __forceinline__ uint32_t pack_h2(float a, float b) {
    __half2 t = __floats2half2_rn(a, b);
    return *reinterpret_cast<uint32_t*>(&t);
}

#define CP_ASYNC16(dst, src) \
    asm volatile("cp.async.cg.shared.global [%0], [%1], 16;" :: "r"(dst), "l"(src))
#define CP_COMMIT() asm volatile("cp.async.commit_group;" ::: "memory")
#define CP_WAIT1()  asm volatile("cp.async.wait_group 1;" ::: "memory")

// ---------------------------------------------------------------------------
// Kernel 0: init min/max accumulators
// ---------------------------------------------------------------------------
__global__ void init_kernel() {
    g_tmin_i = 0x7f800000;   // +inf
    g_tmax_i = 0;            // theta >= 0
}

// ---------------------------------------------------------------------------
// Kernel 1: theta per row (one warp per row) + global min/max
// ---------------------------------------------------------------------------
__global__ void __launch_bounds__(256) theta_kernel(
    const float* __restrict__ x, const float* __restrict__ ray)
{
    __shared__ float sray[D_DIM];
    const int tid = threadIdx.x;
    for (int i = tid; i < D_DIM; i += 256) sray[i] = ray[i];
    __syncthreads();

    const int warp = tid >> 5;
    const int lane = tid & 31;
    const int row  = blockIdx.x * 8 + warp;

    const float* xr = x + (size_t)row * D_DIM;
    float dot = 0.f, ss = 0.f, rss = 0.f;
#pragma unroll
    for (int j = 0; j < 4; j++) {
        float4 xv = reinterpret_cast<const float4*>(xr)[lane + 32 * j];
        float4 rv = reinterpret_cast<const float4*>(sray)[lane + 32 * j];
        dot += xv.x * rv.x + xv.y * rv.y + xv.z * rv.z + xv.w * rv.w;
        ss  += xv.x * xv.x + xv.y * xv.y + xv.z * xv.z + xv.w * xv.w;
        rss += rv.x * rv.x + rv.y * rv.y + rv.z * rv.z + rv.w * rv.w;
    }
#pragma unroll
    for (int o = 16; o > 0; o >>= 1) {
        dot += __shfl_xor_sync(0xffffffffu, dot, o);
        ss  += __shfl_xor_sync(0xffffffffu, ss,  o);
        rss += __shfl_xor_sync(0xffffffffu, rss, o);
    }
    float xn = fmaxf(sqrtf(ss),  1e-8f);
    float rn = fmaxf(sqrtf(rss), 1e-8f);
    float c  = dot / (xn * rn);
    c = fminf(fmaxf(c, -1.0f), 1.0f);
    const float angle = acosf(c) * 0.3183098861837907f;

    if (lane == 0) {
        g_theta[row] = angle;
        atomicMin(&g_tmin_i, __float_as_int(angle));
        atomicMax(&g_tmax_i, __float_as_int(angle));
    }
}

// ---------------------------------------------------------------------------
// Kernel 2: evaluate leaf distribution at the P_N Chebyshev nodes (exact tree)
// ---------------------------------------------------------------------------
__global__ void nodes_kernel(
    const float* __restrict__ w_i, const float* __restrict__ b_i,
    const float* __restrict__ a_i, const int* __restrict__ idx)
{
    const int p = threadIdx.x;
    if (p >= P_N) return;
    float tmin = __int_as_float(g_tmin_i);
    float tmax = __int_as_float(g_tmax_i);
    float c0 = 0.5f * (tmin + tmax);
    float hh = 0.5f * (tmax - tmin) + 1e-6f;
    float th = c0 + hh * c_tp[p];

    float dec[N_NODE];
    for (int n = 0; n < N_NODE; n++) {
        float nf = (0.5f + sigmoidf_(w_i[n])) * th - sigmoidf_(b_i[n]);
        dec[n] = sigmoidf_(nf * (1.0f + a_i[n]));
    }
    for (int l = 0; l < N_LEAF; l++) {
        float pr = 1.0f;
        for (int t = 0; t < 6; t++) {
            int j = idx[l * 6 + t];
            float v = (j < N_NODE) ? dec[j] : (1.0f - dec[j - N_NODE]);
            pr *= v;
        }
        g_Dn[p * N_LEAF + l] = pr;
    }
}

// ---------------------------------------------------------------------------
// Kernel 3: U-build.  g_Ut[p*512+i][w] = sum_l Dn[p][l] * T[l][i][w]  (fp16)
// Block: 256 thr = 64 w x 4 i.  Grid (8 wb, 128 ib).  T read exactly once.
// ---------------------------------------------------------------------------
__global__ void __launch_bounds__(256) ubuild_kernel(const float* __restrict__ T) {
    __shared__ float sDn[P_N * N_LEAF];
    const int tid = threadIdx.x;
    for (int e = tid; e < P_N * N_LEAF; e += 256) sDn[e] = g_Dn[e];
    __syncthreads();

    const int w = blockIdx.x * 64 + (tid & 63);
    const int i = blockIdx.y * 4 + (tid >> 6);

    float acc[P_N];
#pragma unroll
    for (int p = 0; p < P_N; p++) acc[p] = 0.f;

    for (int l = 0; l < N_LEAF; l++) {
        float t = T[((size_t)l * D_DIM + i) * W_DIM + w];
#pragma unroll
        for (int p = 0; p < P_N; p++)
            acc[p] = fmaf(sDn[p * N_LEAF + l], t, acc[p]);
    }
#pragma unroll
    for (int p = 0; p < P_N; p++)
        g_Ut[((size_t)(p * D_DIM + i)) * W_DIM + w] = __float2half_rn(acc[p]);
}

// ---------------------------------------------------------------------------
// Kernel 4: permute U into B-granule tiles (per (nb, kt): 8KB, 512 granules;
// row r=(wslice*4+ks)*32+lane holds {k0,k0+1|n0},{k0+8,k0+9|n0},{..|n1},{..|n1})
// ---------------------------------------------------------------------------
__global__ void __launch_bounds__(256) upermute_kernel() {
    __shared__ unsigned short tile[64][72];   // [k][w]
    const int tid = threadIdx.x;
    const int kt = blockIdx.x;                // 0..95
    const int nb = blockIdx.y;                // 0..7
    const int k0g = kt * 64, w0 = nb * 64;

#pragma unroll
    for (int e = 0; e < 2; e++) {
        int id = tid + e * 256;               // 0..511 uint4 (8 halves each)
        int row = id >> 3, q = id & 7;
        uint4 v = *reinterpret_cast<const uint4*>(
            g_Ut + (size_t)(k0g + row) * W_DIM + w0 + q * 8);
        *reinterpret_cast<uint4*>(&tile[row][q * 8]) = v;
    }
    __syncthreads();

    __half* dst = g_Up + ((size_t)nb * N_KT + kt) * 4096;
#pragma unroll
    for (int t2 = 0; t2 < 2; t2++) {
        int gid = tid + t2 * 256;
        int fid = gid >> 5, ln = gid & 31;
        int ws = fid >> 2, ks = fid & 3;
        int g = ln >> 2, tg = ln & 3;
        int k0 = ks * 16 + 2 * tg;
        int n0 = ws * 16 + g, n1 = n0 + 8;
        uint4 u;
        u.x = (uint32_t)tile[k0][n0]     | ((uint32_t)tile[k0 + 1][n0] << 16);
        u.y = (uint32_t)tile[k0 + 8][n0] | ((uint32_t)tile[k0 + 9][n0] << 16);
        u.z = (uint32_t)tile[k0][n1]     | ((uint32_t)tile[k0 + 1][n1] << 16);
        u.w = (uint32_t)tile[k0 + 8][n1] | ((uint32_t)tile[k0 + 9][n1] << 16);
        *reinterpret_cast<uint4*>(dst + gid * 8) = u;
    }
}

// ---------------------------------------------------------------------------
// Kernel 5: A-build.  A[b][p*512+i] = c_p(theta_b) * x[b][i], written directly
// in A-granule tiles (per (mb, kt): row r=(i16*4+ks)*32+lane ->
// {m,k0..k0+1},{m+8,k0..},{m,k0+8..},{m+8,k0+8..}).  Grid (8 ib, 32 mb).
// ---------------------------------------------------------------------------
__global__ void __launch_bounds__(256) abuild_kernel(const float* __restrict__ x) {
    __shared__ float xs[64][65];
    __shared__ float cf[64][13];
    const int tid = threadIdx.x;
    const int ib = blockIdx.x, mb = blockIdx.y;
    const int m0 = mb * 64, i0 = ib * 64;

#pragma unroll
    for (int e = 0; e < 4; e++) {
        int id = tid + e * 256;               // 0..1023 float4
        int m = id >> 4, q = id & 15;
        float4 v = *reinterpret_cast<const float4*>(x + (size_t)(m0 + m) * D_DIM + i0 + q * 4);
        xs[m][q * 4] = v.x; xs[m][q * 4 + 1] = v.y;
        xs[m][q * 4 + 2] = v.z; xs[m][q * 4 + 3] = v.w;
    }
    if (tid < 64) {
        float tmin = __int_as_float(g_tmin_i);
        float tmax = __int_as_float(g_tmax_i);
        float c0 = 0.5f * (tmin + tmax);
        float hh = 0.5f * (tmax - tmin) + 1e-6f;
        float t = (g_theta[m0 + tid] - c0) / hh;
        float num[P_N];
        float S = 0.f;
        int hit = -1;
#pragma unroll
        for (int p = 0; p < P_N; p++) {
            float d = t - c_tp[p];
            if (fabsf(d) < 1e-7f) hit = p;
            num[p] = c_wp[p] / d;
            S += num[p];
        }
        if (hit >= 0) {
#pragma unroll
            for (int p = 0; p < P_N; p++) cf[tid][p] = (p == hit) ? 1.f : 0.f;
        } else {
            float inv = 1.f / S;
#pragma unroll
            for (int p = 0; p < P_N; p++) cf[tid][p] = num[p] * inv;
        }
    }
    __syncthreads();

#pragma unroll
    for (int p = 0; p < P_N; p++) {
        __half* dst = g_A + ((size_t)mb * N_KT + p * 8 + ib) * 4096;
#pragma unroll
        for (int t2 = 0; t2 < 2; t2++) {
            int gid = tid + t2 * 256;
            int fid = gid >> 5, ln = gid & 31;
            int it_ = fid >> 2, ks = fid & 3;
            int g = ln >> 2, tg = ln & 3;
            int m = it_ * 16 + g;
            int k0 = ks * 16 + 2 * tg;
            float ca = cf[m][p], cb = cf[m + 8][p];
            uint4 u;
            u.x = pack_h2(ca * xs[m][k0],         ca * xs[m][k0 + 1]);
            u.y = pack_h2(cb * xs[m + 8][k0],     cb * xs[m + 8][k0 + 1]);
            u.z = pack_h2(ca * xs[m][k0 + 8],     ca * xs[m][k0 + 9]);
            u.w = pack_h2(cb * xs[m + 8][k0 + 8], cb * xs[m + 8][k0 + 9]);
            *reinterpret_cast<uint4*>(dst + gid * 8) = u;
        }
    }
}

// ---------------------------------------------------------------------------
// Kernel 6: plain fp16 GEMM  out[2048,512] = A[2048,6144] * U[6144,512].
// CTA 64m x 64n, 128 thr = 4 warps by n (warp 64m x 16n). 48 chunks of 128k,
// 3-stage cp.async (A CTA-shared, B warp-private), MMA accumulates into O.
// ---------------------------------------------------------------------------
#define ASM_OFF 0          // 3 x 16384
#define BSM_OFF 49152      // 4 warps x 3 x 4096
#define SMEM_BYTES 98304

__device__ __forceinline__ void issue_chunk(uint32_t sb, int buf, int it,
                                            int mb, int nb, int wid, int tid, int lane) {
    // A: 16 KB = two consecutive kt tiles (contiguous)
    const char* asrc = (const char*)(g_A + ((size_t)mb * N_KT + it * 2) * 4096);
    uint32_t adst = sb + ASM_OFF + buf * 16384;
#pragma unroll
    for (int e = 0; e < 8; e++) {
        uint32_t off = (uint32_t)tid * 16 + e * 2048;
        CP_ASYNC16(adst + off, asrc + off);
    }
    // B: warp's 16n slice of the two kt tiles (2 x 2 KB)
#pragma unroll
    for (int s = 0; s < 2; s++) {
        const char* bsrc = (const char*)(g_Up + ((size_t)nb * N_KT + it * 2 + s) * 4096)
                           + wid * 2048 + lane * 16;
        uint32_t bdst = sb + BSM_OFF + wid * 12288 + buf * 4096 + s * 2048 + lane * 16;
#pragma unroll
        for (int k4 = 0; k4 < 4; k4++)
            CP_ASYNC16(bdst + k4 * 512, bsrc + (size_t)k4 * 512);
    }
}

__global__ void __launch_bounds__(128, 2) gemm_kernel(float* __restrict__ out) {
    extern __shared__ char sm[];
    const uint32_t sb = smem_u32(sm);
    const int tid  = threadIdx.x;
    const int wid  = tid >> 5;
    const int lane = tid & 31;
    const int g    = lane >> 2;
    const int tg   = lane & 3;
    const int nb = blockIdx.x;         // 0..7
    const int mb = blockIdx.y;         // 0..31
    const int m0 = mb * 64;

    float O[4][2][4];
#pragma unroll
    for (int i = 0; i < 4; i++)
#pragma unroll
        for (int j = 0; j < 2; j++)
#pragma unroll
            for (int r = 0; r < 4; r++) O[i][j][r] = 0.f;

    issue_chunk(sb, 0, 0, mb, nb, wid, tid, lane);
    CP_COMMIT();
    issue_chunk(sb, 1, 1, mb, nb, wid, tid, lane);
    CP_COMMIT();

    for (int it = 0; it < N_CHUNK; it++) {
        CP_WAIT1();
        __syncthreads();
        if (it + 2 < N_CHUNK)
            issue_chunk(sb, (it + 2) % 3, it + 2, mb, nb, wid, tid, lane);
        CP_COMMIT();

        const char* ab = sm + ASM_OFF + (it % 3) * 16384;
        const char* bb = sm + BSM_OFF + wid * 12288 + (it % 3) * 4096 + lane * 16;

#pragma unroll
        for (int ks8 = 0; ks8 < 8; ks8++) {
            int s = ks8 >> 2, k4 = ks8 & 3;
            uint4 bv = *reinterpret_cast<const uint4*>(bb + s * 2048 + k4 * 512);
            uint32_t b0[2] = {bv.x, bv.y};
            uint32_t b1[2] = {bv.z, bv.w};
#pragma unroll
            for (int i = 0; i < 4; i++) {
                uint4 av = *reinterpret_cast<const uint4*>(
                    ab + s * 8192 + (i * 4 + k4) * 512 + lane * 16);
                uint32_t a[4] = {av.x, av.y, av.z, av.w};
                mma_f16(O[i][0], a, b0);
                mma_f16(O[i][1], a, b1);
            }
        }
    }

    // Write output fragments
#pragma unroll
    for (int i = 0; i < 4; i++) {
        int r0 = m0 + i * 16 + g;
#pragma unroll
        for (int j = 0; j < 2; j++) {
            int col = nb * 64 + wid * 16 + j * 8 + 2 * tg;
            float2 v0 = make_float2(O[i][j][0], O[i][j][1]);
            float2 v1 = make_float2(O[i][j][2], O[i][j][3]);
            *reinterpret_cast<float2*>(out + (size_t)r0 * W_DIM + col)       = v0;
            *reinterpret_cast<float2*>(out + (size_t)(r0 + 8) * W_DIM + col) = v1;
        }
    }
}

// ---------------------------------------------------------------------------
extern "C" void kernel_launch(void* const* d_in, const int* in_sizes, int n_in,
                              void* d_out, int out_size)
{
    const float* x   = (const float*)d_in[0];
    const float* ray = (const float*)d_in[1];
    const float* w_i = (const float*)d_in[2];
    const float* b_i = (const float*)d_in[3];
    const float* a_i = (const float*)d_in[4];
    const float* T   = (const float*)d_in[5];
    const int*   idx = (const int*)d_in[6];
    float* out = (float*)d_out;

    cudaFuncSetAttribute(gemm_kernel,
                         cudaFuncAttributeMaxDynamicSharedMemorySize, SMEM_BYTES);

    init_kernel<<<1, 1>>>();
    theta_kernel<<<B_ROWS / 8, 256>>>(x, ray);
    nodes_kernel<<<1, 32>>>(w_i, b_i, a_i, idx);
    ubuild_kernel<<<dim3(8, 128), 256>>>(T);
    upermute_kernel<<<dim3(N_KT, 8), 256>>>();
    abuild_kernel<<<dim3(8, 32), 256>>>(x);
    gemm_kernel<<<dim3(8, 32), 128, SMEM_BYTES>>>(out);
}

// round 13
// speedup vs baseline: 2.7434x; 1.2741x over previous
#include <cuda_runtime.h>
#include <cuda_fp16.h>
#include <math.h>
#include <stdint.h>

#define B_ROWS 2048
#define D_DIM  512
#define W_DIM  512
#define N_LEAF 64
#define N_NODE 63
#define P_N    12
#define K_TOT  (P_N * D_DIM)     // 6144
#define N_KT   (K_TOT / 64)      // 96 kc64 tiles
#define NIT    48                // 4 k-chunks x 12 nodes

// ---------------------------------------------------------------------------
// Device scratch (no cudaMalloc allowed)
// ---------------------------------------------------------------------------
__device__ float  g_theta[B_ROWS];
__device__ int    g_tmin_i, g_tmax_i;
__device__ float  g_Dn[P_N * N_LEAF];                        // d_l at nodes
__device__ __half g_Ut[(size_t)K_TOT * W_DIM];               // U row-major
__device__ __half g_Up[(size_t)(W_DIM / 64) * N_KT * 4096];  // U granules

// Chebyshev-1 nodes on [-1,1] and barycentric weights (canonical)
__device__ __constant__ float c_tp[12] = {
    0.9914448614f,  0.9238795325f,  0.7933533403f,  0.6087614290f,
    0.3826834324f,  0.1305261922f, -0.1305261922f, -0.3826834324f,
   -0.6087614290f, -0.7933533403f, -0.9238795325f, -0.9914448614f };
__device__ __constant__ float c_wp[12] = {
    0.1305261922f, -0.3826834324f,  0.6087614290f, -0.7933533403f,
    0.9238795325f, -0.9914448614f,  0.9914448614f, -0.9238795325f,
    0.7933533403f, -0.6087614290f,  0.3826834324f, -0.1305261922f };

// ---------------------------------------------------------------------------
// Helpers
// ---------------------------------------------------------------------------
__device__ __forceinline__ uint32_t smem_u32(const void* p) {
    uint32_t a;
    asm("{ .reg .u64 t; cvta.to.shared.u64 t, %1; cvt.u32.u64 %0, t; }"
        : "=r"(a) : "l"(p));
    return a;
}

__device__ __forceinline__ float sigmoidf_(float z) { return 1.0f / (1.0f + expf(-z)); }

__device__ __forceinline__ void mma_f16(float c[4], const uint32_t a[4], const uint32_t b[2]) {
    asm volatile("mma.sync.aligned.m16n8k16.row.col.f32.f16.f16.f32 "
                 "{%0,%1,%2,%3}, {%4,%5,%6,%7}, {%8,%9}, {%0,%1,%2,%3};"
                 : "+f"(c[0]), "+f"(c[1]), "+f"(c[2]), "+f"(c[3])
                 : "r"(a[0]), "r"(a[1]), "r"(a[2]), "r"(a[3]), "r"(b[0]), "r"(b[1]));
}

__device__ __forceinline__ uint32_t pack_h2(float a, float b) {
    __half2 t = __floats2half2_rn(a, b);
    return *reinterpret_cast<uint32_t*>(&t);
}

#define CP_ASYNC16(dst, src) \
    asm volatile("cp.async.cg.shared.global [%0], [%1], 16;" :: "r"(dst), "l"(src))
#define CP_COMMIT() asm volatile("cp.async.commit_group;" ::: "memory")
#define CP_WAIT1()  asm volatile("cp.async.wait_group 1;" ::: "memory")

// ---------------------------------------------------------------------------
// Kernel 0: init min/max accumulators
// ---------------------------------------------------------------------------
__global__ void init_kernel() {
    g_tmin_i = 0x7f800000;
    g_tmax_i = 0;
}

// ---------------------------------------------------------------------------
// Kernel 1: theta per row (one warp per row) + global min/max
// ---------------------------------------------------------------------------
__global__ void __launch_bounds__(256) theta_kernel(
    const float* __restrict__ x, const float* __restrict__ ray)
{
    __shared__ float sray[D_DIM];
    const int tid = threadIdx.x;
    for (int i = tid; i < D_DIM; i += 256) sray[i] = ray[i];
    __syncthreads();

    const int warp = tid >> 5;
    const int lane = tid & 31;
    const int row  = blockIdx.x * 8 + warp;

    const float* xr = x + (size_t)row * D_DIM;
    float dot = 0.f, ss = 0.f, rss = 0.f;
#pragma unroll
    for (int j = 0; j < 4; j++) {
        float4 xv = reinterpret_cast<const float4*>(xr)[lane + 32 * j];
        float4 rv = reinterpret_cast<const float4*>(sray)[lane + 32 * j];
        dot += xv.x * rv.x + xv.y * rv.y + xv.z * rv.z + xv.w * rv.w;
        ss  += xv.x * xv.x + xv.y * xv.y + xv.z * xv.z + xv.w * xv.w;
        rss += rv.x * rv.x + rv.y * rv.y + rv.z * rv.z + rv.w * rv.w;
    }
#pragma unroll
    for (int o = 16; o > 0; o >>= 1) {
        dot += __shfl_xor_sync(0xffffffffu, dot, o);
        ss  += __shfl_xor_sync(0xffffffffu, ss,  o);
        rss += __shfl_xor_sync(0xffffffffu, rss, o);
    }
    float xn = fmaxf(sqrtf(ss),  1e-8f);
    float rn = fmaxf(sqrtf(rss), 1e-8f);
    float c  = dot / (xn * rn);
    c = fminf(fmaxf(c, -1.0f), 1.0f);
    const float angle = acosf(c) * 0.3183098861837907f;

    if (lane == 0) {
        g_theta[row] = angle;
        atomicMin(&g_tmin_i, __float_as_int(angle));
        atomicMax(&g_tmax_i, __float_as_int(angle));
    }
}

// ---------------------------------------------------------------------------
// Kernel 2: evaluate leaf distribution at the P_N Chebyshev nodes (exact tree)
// ---------------------------------------------------------------------------
__global__ void nodes_kernel(
    const float* __restrict__ w_i, const float* __restrict__ b_i,
    const float* __restrict__ a_i, const int* __restrict__ idx)
{
    const int p = threadIdx.x;
    if (p >= P_N) return;
    float tmin = __int_as_float(g_tmin_i);
    float tmax = __int_as_float(g_tmax_i);
    float c0 = 0.5f * (tmin + tmax);
    float hh = 0.5f * (tmax - tmin) + 1e-6f;
    float th = c0 + hh * c_tp[p];

    float dec[N_NODE];
    for (int n = 0; n < N_NODE; n++) {
        float nf = (0.5f + sigmoidf_(w_i[n])) * th - sigmoidf_(b_i[n]);
        dec[n] = sigmoidf_(nf * (1.0f + a_i[n]));
    }
    for (int l = 0; l < N_LEAF; l++) {
        float pr = 1.0f;
        for (int t = 0; t < 6; t++) {
            int j = idx[l * 6 + t];
            float v = (j < N_NODE) ? dec[j] : (1.0f - dec[j - N_NODE]);
            pr *= v;
        }
        g_Dn[p * N_LEAF + l] = pr;
    }
}

// ---------------------------------------------------------------------------
// Kernel 3: U-build (vectorized). g_Ut[p*512+i][w] = sum_l Dn[p][l]*T[l][i][w].
// Block 256 thr: 128 w-float4 x 2 i.  Grid 256 (i pairs).  T read once, float4.
// ---------------------------------------------------------------------------
__global__ void __launch_bounds__(256) ubuild_kernel(const float* __restrict__ T) {
    __shared__ float sDn[P_N * N_LEAF];
    const int tid = threadIdx.x;
    for (int e = tid; e < P_N * N_LEAF; e += 256) sDn[e] = g_Dn[e];
    __syncthreads();

    const int w4 = tid & 127;                 // float4 index (w = w4*4)
    const int i  = blockIdx.x * 2 + (tid >> 7);

    float acc[P_N][4];
#pragma unroll
    for (int p = 0; p < P_N; p++)
#pragma unroll
        for (int q = 0; q < 4; q++) acc[p][q] = 0.f;

    const float* tp = T + (size_t)i * W_DIM + (size_t)w4 * 4;
#pragma unroll 4
    for (int l = 0; l < N_LEAF; l++) {
        float4 t = *reinterpret_cast<const float4*>(tp + (size_t)l * D_DIM * W_DIM);
#pragma unroll
        for (int p = 0; p < P_N; p++) {
            float s = sDn[p * N_LEAF + l];
            acc[p][0] = fmaf(s, t.x, acc[p][0]);
            acc[p][1] = fmaf(s, t.y, acc[p][1]);
            acc[p][2] = fmaf(s, t.z, acc[p][2]);
            acc[p][3] = fmaf(s, t.w, acc[p][3]);
        }
    }
#pragma unroll
    for (int p = 0; p < P_N; p++) {
        uint2 u = make_uint2(pack_h2(acc[p][0], acc[p][1]),
                             pack_h2(acc[p][2], acc[p][3]));
        *reinterpret_cast<uint2*>(g_Ut + ((size_t)(p * D_DIM + i)) * W_DIM + w4 * 4) = u;
    }
}

// ---------------------------------------------------------------------------
// Kernel 4: permute U into B-granule tiles (per (nb, kt): 8KB, 512 rows;
// row r=(ws*4+ks)*32+lane holds {k0,k0+1|n0},{k0+8,k0+9|n0},{..|n1},{..|n1})
// ---------------------------------------------------------------------------
__global__ void __launch_bounds__(256) upermute_kernel() {
    __shared__ unsigned short tile[64][72];   // [k][w]
    const int tid = threadIdx.x;
    const int kt = blockIdx.x;                // 0..95
    const int nb = blockIdx.y;                // 0..7
    const int k0g = kt * 64, w0 = nb * 64;

#pragma unroll
    for (int e = 0; e < 2; e++) {
        int id = tid + e * 256;
        int row = id >> 3, q = id & 7;
        uint4 v = *reinterpret_cast<const uint4*>(
            g_Ut + (size_t)(k0g + row) * W_DIM + w0 + q * 8);
        *reinterpret_cast<uint4*>(&tile[row][q * 8]) = v;
    }
    __syncthreads();

    __half* dst = g_Up + ((size_t)nb * N_KT + kt) * 4096;
#pragma unroll
    for (int t2 = 0; t2 < 2; t2++) {
        int gid = tid + t2 * 256;
        int fid = gid >> 5, ln = gid & 31;
        int ws = fid >> 2, ks = fid & 3;
        int g = ln >> 2, tg = ln & 3;
        int k0 = ks * 16 + 2 * tg;
        int n0 = ws * 16 + g, n1 = n0 + 8;
        uint4 u;
        u.x = (uint32_t)tile[k0][n0]     | ((uint32_t)tile[k0 + 1][n0] << 16);
        u.y = (uint32_t)tile[k0 + 8][n0] | ((uint32_t)tile[k0 + 9][n0] << 16);
        u.z = (uint32_t)tile[k0][n1]     | ((uint32_t)tile[k0 + 1][n1] << 16);
        u.w = (uint32_t)tile[k0 + 8][n1] | ((uint32_t)tile[k0 + 9][n1] << 16);
        *reinterpret_cast<uint4*>(dst + gid * 8) = u;
    }
}

// ---------------------------------------------------------------------------
// Kernel 5: GEMM with on-the-fly A.  out[b,w] = sum_p cf[b,p] (x_b . U_p)[w].
// CTA 128m x 64n, 256 thr = 8 warps (4m x 2n), warp tile 32m x 32n.
// it = chunk*12 + p over 48 iterations (4 chunks of 128k).  X (x fp16)
// register-resident per chunk; B (U granules) 3-stage cp.async; epilogue
// scales the per-p partial product by cf[row][p].
// ---------------------------------------------------------------------------
// smem: XW [128 rows][68 words] @0 (34816) | B 3x16384 @34816 | cf @83968
#define XWOFF  0
#define BOFF   34816
#define CFOFF  83968
#define SMEM_BYTES (83968 + 6144)

__device__ __forceinline__ void issue_b(uint32_t sb, int buf, int p, int chunk,
                                        int nb, int tid) {
    const char* src = (const char*)(g_Up + ((size_t)nb * N_KT + p * 8 + chunk * 2) * 4096);
    uint32_t dst = sb + BOFF + buf * 16384;
#pragma unroll
    for (int e = 0; e < 4; e++) {
        uint32_t off = (uint32_t)(tid + e * 256) * 16;
        CP_ASYNC16(dst + off, src + off);
    }
}

__global__ void __launch_bounds__(256, 1) gemm_kernel(
    const float* __restrict__ x, float* __restrict__ out)
{
    extern __shared__ char sm[];
    const uint32_t sb = smem_u32(sm);
    const int tid  = threadIdx.x;
    const int wid  = tid >> 5;
    const int lane = tid & 31;
    const int wm   = wid & 3;        // 4 m-warps (32 rows each)
    const int wn   = wid >> 2;       // 2 n-warps (32 cols each)
    const int g    = lane >> 2;
    const int tg   = lane & 3;
    const int nb = blockIdx.x;       // 0..7
    const int mb = blockIdx.y;       // 0..15
    const int m0 = mb * 128;

    uint32_t* XW = reinterpret_cast<uint32_t*>(sm + XWOFF);  // pitch 68 words
    float*    CF = reinterpret_cast<float*>(sm + CFOFF);     // [128][12]

    // Barycentric coefficients for this CTA's 128 rows
    if (tid < 128) {
        float tmin = __int_as_float(g_tmin_i);
        float tmax = __int_as_float(g_tmax_i);
        float c0 = 0.5f * (tmin + tmax);
        float hh = 0.5f * (tmax - tmin) + 1e-6f;
        float t = (g_theta[m0 + tid] - c0) / hh;
        float num[P_N];
        float S = 0.f;
        int hit = -1;
#pragma unroll
        for (int p = 0; p < P_N; p++) {
            float d = t - c_tp[p];
            if (fabsf(d) < 1e-7f) hit = p;
            num[p] = c_wp[p] / d;
            S += num[p];
        }
        if (hit >= 0) {
#pragma unroll
            for (int p = 0; p < P_N; p++) CF[tid * 12 + p] = (p == hit) ? 1.f : 0.f;
        } else {
            float inv = 1.f / S;
#pragma unroll
            for (int p = 0; p < P_N; p++) CF[tid * 12 + p] = num[p] * inv;
        }
    }

    float O[2][4][4];
#pragma unroll
    for (int i = 0; i < 2; i++)
#pragma unroll
        for (int j = 0; j < 4; j++)
#pragma unroll
            for (int r = 0; r < 4; r++) O[i][j][r] = 0.f;

    // Prologue: B for it=0 (p0,c0) and it=1 (p1,c0)
    issue_b(sb, 0, 0, 0, nb, tid);
    CP_COMMIT();
    issue_b(sb, 1, 1, 0, nb, tid);
    CP_COMMIT();

    uint32_t A[8][2][4];   // x fragments for the 128k chunk (per warp: 32m)

    int p = 0, chunk = 0;
    int p2 = 2, ch2 = 0;

    for (int it = 0; it < NIT; it++) {
        CP_WAIT1();
        __syncthreads();

        if (p == 0) {
            // ---- rebuild X [128m x 128k] fp16 from x fp32 (4 times total) ----
            const float* xp = x + (size_t)m0 * D_DIM + chunk * 128;
#pragma unroll
            for (int e = 0; e < 16; e++) {
                int id = tid + e * 256;         // 0..4095 float4 (128 rows x 32)
                int m = id >> 5, q = id & 31;
                float4 v = *reinterpret_cast<const float4*>(xp + (size_t)m * D_DIM + q * 4);
                uint2 u = make_uint2(pack_h2(v.x, v.y), pack_h2(v.z, v.w));
                *reinterpret_cast<uint2*>(XW + m * 68 + q * 2) = u;
            }
            __syncthreads();
#pragma unroll
            for (int ks = 0; ks < 8; ks++) {
#pragma unroll
                for (int i = 0; i < 2; i++) {
                    int m = wm * 32 + i * 16 + g;
                    int k = ks * 8 + tg;
                    A[ks][i][0] = XW[m * 68 + k];
                    A[ks][i][1] = XW[(m + 8) * 68 + k];
                    A[ks][i][2] = XW[m * 68 + k + 4];
                    A[ks][i][3] = XW[(m + 8) * 68 + k + 4];
                }
            }
        }

        if (it + 2 < NIT)
            issue_b(sb, (it + 2) % 3, p2, ch2, nb, tid);
        CP_COMMIT();

        const char* Bb = sm + BOFF + (it % 3) * 16384;

        float P[2][4][4];
#pragma unroll
        for (int i = 0; i < 2; i++)
#pragma unroll
            for (int j = 0; j < 4; j++)
#pragma unroll
                for (int r = 0; r < 4; r++) P[i][j][r] = 0.f;

#pragma unroll
        for (int ks = 0; ks < 8; ks++) {
            int s = ks >> 2, k4 = ks & 3;
            uint4 b0v = *reinterpret_cast<const uint4*>(
                Bb + s * 8192 + ((wn * 2 + 0) * 4 + k4) * 512 + lane * 16);
            uint4 b1v = *reinterpret_cast<const uint4*>(
                Bb + s * 8192 + ((wn * 2 + 1) * 4 + k4) * 512 + lane * 16);
            uint32_t b[4][2];
            b[0][0] = b0v.x; b[0][1] = b0v.y;
            b[1][0] = b0v.z; b[1][1] = b0v.w;
            b[2][0] = b1v.x; b[2][1] = b1v.y;
            b[3][0] = b1v.z; b[3][1] = b1v.w;
#pragma unroll
            for (int i = 0; i < 2; i++)
#pragma unroll
                for (int j = 0; j < 4; j++)
                    mma_f16(P[i][j], A[ks][i], b[j]);
        }

        // Epilogue: O += cf[row, p] * P
#pragma unroll
        for (int i = 0; i < 2; i++) {
            int r0 = wm * 32 + i * 16 + g;
            float d0 = CF[r0 * 12 + p];
            float d1 = CF[(r0 + 8) * 12 + p];
#pragma unroll
            for (int j = 0; j < 4; j++) {
                O[i][j][0] = fmaf(d0, P[i][j][0], O[i][j][0]);
                O[i][j][1] = fmaf(d0, P[i][j][1], O[i][j][1]);
                O[i][j][2] = fmaf(d1, P[i][j][2], O[i][j][2]);
                O[i][j][3] = fmaf(d1, P[i][j][3], O[i][j][3]);
            }
        }

        if (++p == P_N)  { p = 0;  chunk++; }
        if (++p2 == P_N) { p2 = 0; ch2++; }
    }

    // Write output fragments
#pragma unroll
    for (int i = 0; i < 2; i++) {
        int r0 = m0 + wm * 32 + i * 16 + g;
#pragma unroll
        for (int j = 0; j < 4; j++) {
            int col = nb * 64 + wn * 32 + j * 8 + 2 * tg;
            float2 v0 = make_float2(O[i][j][0], O[i][j][1]);
            float2 v1 = make_float2(O[i][j][2], O[i][j][3]);
            *reinterpret_cast<float2*>(out + (size_t)r0 * W_DIM + col)       = v0;
            *reinterpret_cast<float2*>(out + (size_t)(r0 + 8) * W_DIM + col) = v1;
        }
    }
}

// ---------------------------------------------------------------------------
extern "C" void kernel_launch(void* const* d_in, const int* in_sizes, int n_in,
                              void* d_out, int out_size)
{
    const float* x   = (const float*)d_in[0];
    const float* ray = (const float*)d_in[1];
    const float* w_i = (const float*)d_in[2];
    const float* b_i = (const float*)d_in[3];
    const float* a_i = (const float*)d_in[4];
    const float* T   = (const float*)d_in[5];
    const int*   idx = (const int*)d_in[6];
    float* out = (float*)d_out;

    cudaFuncSetAttribute(gemm_kernel,
                         cudaFuncAttributeMaxDynamicSharedMemorySize, SMEM_BYTES);

    init_kernel<<<1, 1>>>();
    theta_kernel<<<B_ROWS / 8, 256>>>(x, ray);
    nodes_kernel<<<1, 32>>>(w_i, b_i, a_i, idx);
    ubuild_kernel<<<D_DIM / 2, 256>>>(T);
    upermute_kernel<<<dim3(N_KT, 8), 256>>>();
    gemm_kernel<<<dim3(8, 16), 256, SMEM_BYTES>>>(x, out);
}

// round 14
// speedup vs baseline: 3.0007x; 1.0938x over previous
#include <cuda_runtime.h>
#include <cuda_fp16.h>
#include <math.h>
#include <stdint.h>

#define B_ROWS 2048
#define D_DIM  512
#define W_DIM  512
#define N_LEAF 64
#define N_NODE 63
#define P_N    8
#define K_TOT  (P_N * D_DIM)     // 4096
#define N_KT   (K_TOT / 64)      // 64 kc64 tiles
#define NIT    64                // 8 i-chunks x 8 nodes

// ---------------------------------------------------------------------------
// Device scratch (no cudaMalloc allowed)
// ---------------------------------------------------------------------------
__device__ float  g_theta[B_ROWS];
__device__ int    g_tmin_i, g_tmax_i;
__device__ float  g_Dn[P_N * N_LEAF];                        // d_l at nodes
__device__ __half g_Ut[(size_t)K_TOT * W_DIM];               // U row-major
__device__ __half g_Up[(size_t)(W_DIM / 64) * N_KT * 4096];  // U granules

// Chebyshev-1 nodes (P=8) on [-1,1] and barycentric weights (canonical)
__device__ __constant__ float c_tp[P_N] = {
    0.98078528f,  0.83146961f,  0.55557023f,  0.19509032f,
   -0.19509032f, -0.55557023f, -0.83146961f, -0.98078528f };
__device__ __constant__ float c_wp[P_N] = {
    0.19509032f, -0.55557023f,  0.83146961f, -0.98078528f,
    0.98078528f, -0.83146961f,  0.55557023f, -0.19509032f };

// ---------------------------------------------------------------------------
// Helpers
// ---------------------------------------------------------------------------
__device__ __forceinline__ uint32_t smem_u32(const void* p) {
    uint32_t a;
    asm("{ .reg .u64 t; cvta.to.shared.u64 t, %1; cvt.u32.u64 %0, t; }"
        : "=r"(a) : "l"(p));
    return a;
}

__device__ __forceinline__ float sigmoidf_(float z) { return 1.0f / (1.0f + expf(-z)); }

__device__ __forceinline__ void mma_f16(float c[4], const uint32_t a[4], const uint32_t b[2]) {
    asm volatile("mma.sync.aligned.m16n8k16.row.col.f32.f16.f16.f32 "
                 "{%0,%1,%2,%3}, {%4,%5,%6,%7}, {%8,%9}, {%0,%1,%2,%3};"
                 : "+f"(c[0]), "+f"(c[1]), "+f"(c[2]), "+f"(c[3])
                 : "r"(a[0]), "r"(a[1]), "r"(a[2]), "r"(a[3]), "r"(b[0]), "r"(b[1]));
}

__device__ __forceinline__ uint32_t pack_h2(float a, float b) {
    __half2 t = __floats2half2_rn(a, b);
    return *reinterpret_cast<uint32_t*>(&t);
}

#define CP_ASYNC16(dst, src) \
    asm volatile("cp.async.cg.shared.global [%0], [%1], 16;" :: "r"(dst), "l"(src))
#define CP_COMMIT() asm volatile("cp.async.commit_group;" ::: "memory")
#define CP_WAIT1()  asm volatile("cp.async.wait_group 1;" ::: "memory")

// ---------------------------------------------------------------------------
// Kernel 0: init min/max accumulators
// ---------------------------------------------------------------------------
__global__ void init_kernel() {
    g_tmin_i = 0x7f800000;
    g_tmax_i = 0;
}

// ---------------------------------------------------------------------------
// Kernel 1: theta per row (one warp per row) + global min/max
// ---------------------------------------------------------------------------
__global__ void __launch_bounds__(256) theta_kernel(
    const float* __restrict__ x, const float* __restrict__ ray)
{
    __shared__ float sray[D_DIM];
    const int tid = threadIdx.x;
    for (int i = tid; i < D_DIM; i += 256) sray[i] = ray[i];
    __syncthreads();

    const int warp = tid >> 5;
    const int lane = tid & 31;
    const int row  = blockIdx.x * 8 + warp;

    const float* xr = x + (size_t)row * D_DIM;
    float dot = 0.f, ss = 0.f, rss = 0.f;
#pragma unroll
    for (int j = 0; j < 4; j++) {
        float4 xv = reinterpret_cast<const float4*>(xr)[lane + 32 * j];
        float4 rv = reinterpret_cast<const float4*>(sray)[lane + 32 * j];
        dot += xv.x * rv.x + xv.y * rv.y + xv.z * rv.z + xv.w * rv.w;
        ss  += xv.x * xv.x + xv.y * xv.y + xv.z * xv.z + xv.w * xv.w;
        rss += rv.x * rv.x + rv.y * rv.y + rv.z * rv.z + rv.w * rv.w;
    }
#pragma unroll
    for (int o = 16; o > 0; o >>= 1) {
        dot += __shfl_xor_sync(0xffffffffu, dot, o);
        ss  += __shfl_xor_sync(0xffffffffu, ss,  o);
        rss += __shfl_xor_sync(0xffffffffu, rss, o);
    }
    float xn = fmaxf(sqrtf(ss),  1e-8f);
    float rn = fmaxf(sqrtf(rss), 1e-8f);
    float c  = dot / (xn * rn);
    c = fminf(fmaxf(c, -1.0f), 1.0f);
    const float angle = acosf(c) * 0.3183098861837907f;

    if (lane == 0) {
        g_theta[row] = angle;
        atomicMin(&g_tmin_i, __float_as_int(angle));
        atomicMax(&g_tmax_i, __float_as_int(angle));
    }
}

// ---------------------------------------------------------------------------
// Kernel 2: evaluate leaf distribution at the P_N Chebyshev nodes (exact tree)
// ---------------------------------------------------------------------------
__global__ void nodes_kernel(
    const float* __restrict__ w_i, const float* __restrict__ b_i,
    const float* __restrict__ a_i, const int* __restrict__ idx)
{
    const int p = threadIdx.x;
    if (p >= P_N) return;
    float tmin = __int_as_float(g_tmin_i);
    float tmax = __int_as_float(g_tmax_i);
    float c0 = 0.5f * (tmin + tmax);
    float hh = 0.5f * (tmax - tmin) + 1e-6f;
    float th = c0 + hh * c_tp[p];

    float dec[N_NODE];
    for (int n = 0; n < N_NODE; n++) {
        float nf = (0.5f + sigmoidf_(w_i[n])) * th - sigmoidf_(b_i[n]);
        dec[n] = sigmoidf_(nf * (1.0f + a_i[n]));
    }
    for (int l = 0; l < N_LEAF; l++) {
        float pr = 1.0f;
        for (int t = 0; t < 6; t++) {
            int j = idx[l * 6 + t];
            float v = (j < N_NODE) ? dec[j] : (1.0f - dec[j - N_NODE]);
            pr *= v;
        }
        g_Dn[p * N_LEAF + l] = pr;
    }
}

// ---------------------------------------------------------------------------
// Kernel 3: U-build.  g_Ut[p*512+i][w] = sum_l Dn[p][l]*T[l][i][w].
// Grid 512 (one i per block); block 256 = 128 w-float4 x 2 leaf-halves;
// smem reduction combines the halves.  T read exactly once (float4).
// ---------------------------------------------------------------------------
__global__ void __launch_bounds__(256) ubuild_kernel(const float* __restrict__ T) {
    __shared__ float sDn[P_N * N_LEAF];
    __shared__ float red[128 * P_N * 4];      // 16 KB partials from half 1
    const int tid = threadIdx.x;
    for (int e = tid; e < P_N * N_LEAF; e += 256) sDn[e] = g_Dn[e];
    __syncthreads();

    const int w4 = tid & 127;
    const int lh = tid >> 7;                  // leaf half
    const int i  = blockIdx.x;

    float acc[P_N][4];
#pragma unroll
    for (int p = 0; p < P_N; p++)
#pragma unroll
        for (int q = 0; q < 4; q++) acc[p][q] = 0.f;

    const float* tp = T + ((size_t)(lh * 32) * D_DIM + i) * W_DIM + (size_t)w4 * 4;
#pragma unroll 4
    for (int l = 0; l < 32; l++) {
        float4 t = *reinterpret_cast<const float4*>(tp + (size_t)l * D_DIM * W_DIM);
        const float* dn = sDn + (lh * 32 + l);
#pragma unroll
        for (int p = 0; p < P_N; p++) {
            float s = dn[p * N_LEAF];
            acc[p][0] = fmaf(s, t.x, acc[p][0]);
            acc[p][1] = fmaf(s, t.y, acc[p][1]);
            acc[p][2] = fmaf(s, t.z, acc[p][2]);
            acc[p][3] = fmaf(s, t.w, acc[p][3]);
        }
    }

    if (lh == 1) {
#pragma unroll
        for (int p = 0; p < P_N; p++)
            *reinterpret_cast<float4*>(red + (p * 128 + w4) * 4) =
                make_float4(acc[p][0], acc[p][1], acc[p][2], acc[p][3]);
    }
    __syncthreads();
    if (lh == 0) {
#pragma unroll
        for (int p = 0; p < P_N; p++) {
            float4 r = *reinterpret_cast<const float4*>(red + (p * 128 + w4) * 4);
            uint2 u = make_uint2(pack_h2(acc[p][0] + r.x, acc[p][1] + r.y),
                                 pack_h2(acc[p][2] + r.z, acc[p][3] + r.w));
            *reinterpret_cast<uint2*>(g_Ut + ((size_t)(p * D_DIM + i)) * W_DIM + w4 * 4) = u;
        }
    }
}

// ---------------------------------------------------------------------------
// Kernel 4: permute U into B-granule tiles (per (nb64, kt): 8KB, 512 rows;
// row r=(ws*4+ks)*32+lane holds {k0,k0+1|n0},{k0+8,k0+9|n0},{..|n1},{..|n1})
// ---------------------------------------------------------------------------
__global__ void __launch_bounds__(256) upermute_kernel() {
    __shared__ unsigned short tile[64][72];   // [k][w]
    const int tid = threadIdx.x;
    const int kt = blockIdx.x;                // 0..63
    const int nb = blockIdx.y;                // 0..7
    const int k0g = kt * 64, w0 = nb * 64;

#pragma unroll
    for (int e = 0; e < 2; e++) {
        int id = tid + e * 256;
        int row = id >> 3, q = id & 7;
        uint4 v = *reinterpret_cast<const uint4*>(
            g_Ut + (size_t)(k0g + row) * W_DIM + w0 + q * 8);
        *reinterpret_cast<uint4*>(&tile[row][q * 8]) = v;
    }
    __syncthreads();

    __half* dst = g_Up + ((size_t)nb * N_KT + kt) * 4096;
#pragma unroll
    for (int t2 = 0; t2 < 2; t2++) {
        int gid = tid + t2 * 256;
        int fid = gid >> 5, ln = gid & 31;
        int ws = fid >> 2, ks = fid & 3;
        int g = ln >> 2, tg = ln & 3;
        int k0 = ks * 16 + 2 * tg;
        int n0 = ws * 16 + g, n1 = n0 + 8;
        uint4 u;
        u.x = (uint32_t)tile[k0][n0]     | ((uint32_t)tile[k0 + 1][n0] << 16);
        u.y = (uint32_t)tile[k0 + 8][n0] | ((uint32_t)tile[k0 + 9][n0] << 16);
        u.z = (uint32_t)tile[k0][n1]     | ((uint32_t)tile[k0 + 1][n1] << 16);
        u.w = (uint32_t)tile[k0 + 8][n1] | ((uint32_t)tile[k0 + 9][n1] << 16);
        *reinterpret_cast<uint4*>(dst + gid * 8) = u;
    }
}

// ---------------------------------------------------------------------------
// Kernel 5: GEMM with on-the-fly A.  out[b,w] = sum_p cf[b,p] (x_b . U_p)[w].
// CTA 128m x 32n, 256 thr = 8 warps (4m x 2n), warp tile 32m x 16n.
// it = ic*8 + p over 64 iterations (8 i-chunks of 64k).  X fragments
// register-resident per chunk; B 3-stage cp.async (4KB tiles, 1 granule/thr);
// epilogue scales the per-p partial product by cf[row][p].  2 CTAs/SM.
// ---------------------------------------------------------------------------
// smem: XW [128 rows][36 words] @0 (18432) | B 3x4096 @18432 | CF @30720 (4096)
#define XWOFF  0
#define BOFF   18432
#define CFOFF  30720
#define SMEM_BYTES 34816

__device__ __forceinline__ void issue_b(uint32_t sb, int buf, int p, int ic,
                                        int nb64, int h, int tid) {
    int ws2 = tid >> 7, ks = (tid >> 5) & 3, ln = tid & 31;
    const char* src = (const char*)(g_Up + ((size_t)nb64 * N_KT + p * 8 + ic) * 4096)
                      + ((2 * h + ws2) * 4 + ks) * 512 + ln * 16;
    uint32_t dst = sb + BOFF + buf * 4096 + ((ws2 * 4 + ks) * 512 + ln * 16);
    CP_ASYNC16(dst, src);
}

__global__ void __launch_bounds__(256, 2) gemm_kernel(
    const float* __restrict__ x, float* __restrict__ out)
{
    extern __shared__ char sm[];
    const uint32_t sb = smem_u32(sm);
    const int tid  = threadIdx.x;
    const int wid  = tid >> 5;
    const int lane = tid & 31;
    const int wm   = wid & 3;        // 4 m-warps (32 rows each)
    const int wn   = wid >> 2;       // 2 n-warps (16 cols each)
    const int g    = lane >> 2;
    const int tg   = lane & 3;
    const int nb32 = blockIdx.x;     // 0..15
    const int nb64 = nb32 >> 1;
    const int h    = nb32 & 1;
    const int mb = blockIdx.y;       // 0..15
    const int m0 = mb * 128;

    uint32_t* XW = reinterpret_cast<uint32_t*>(sm + XWOFF);  // pitch 36 words
    float*    CF = reinterpret_cast<float*>(sm + CFOFF);     // [128][8]

    // Barycentric coefficients for this CTA's 128 rows
    if (tid < 128) {
        float tmin = __int_as_float(g_tmin_i);
        float tmax = __int_as_float(g_tmax_i);
        float c0 = 0.5f * (tmin + tmax);
        float hh = 0.5f * (tmax - tmin) + 1e-6f;
        float t = (g_theta[m0 + tid] - c0) / hh;
        float num[P_N];
        float S = 0.f;
        int hit = -1;
#pragma unroll
        for (int p = 0; p < P_N; p++) {
            float d = t - c_tp[p];
            if (fabsf(d) < 1e-7f) hit = p;
            num[p] = c_wp[p] / d;
            S += num[p];
        }
        if (hit >= 0) {
#pragma unroll
            for (int p = 0; p < P_N; p++) CF[tid * P_N + p] = (p == hit) ? 1.f : 0.f;
        } else {
            float inv = 1.f / S;
#pragma unroll
            for (int p = 0; p < P_N; p++) CF[tid * P_N + p] = num[p] * inv;
        }
    }

    float O[2][2][4];
#pragma unroll
    for (int i = 0; i < 2; i++)
#pragma unroll
        for (int j = 0; j < 2; j++)
#pragma unroll
            for (int r = 0; r < 4; r++) O[i][j][r] = 0.f;

    // Prologue: B for it=0 (ic0,p0) and it=1 (ic0,p1)
    issue_b(sb, 0, 0, 0, nb64, h, tid);
    CP_COMMIT();
    issue_b(sb, 1, 1, 0, nb64, h, tid);
    CP_COMMIT();

    uint32_t A[4][2][4];   // x fragments for the 64k chunk

    for (int it = 0; it < NIT; it++) {
        const int p = it & 7;

        CP_WAIT1();
        __syncthreads();

        if (p == 0) {
            // ---- rebuild X [128m x 64k] fp16 from x fp32 (8 times total) ----
            const float* xp = x + (size_t)m0 * D_DIM + (it >> 3) * 64;
#pragma unroll
            for (int e = 0; e < 8; e++) {
                int id = tid + e * 256;         // 0..2047 float4 (128 rows x 16)
                int m = id >> 4, q = id & 15;
                float4 v = *reinterpret_cast<const float4*>(xp + (size_t)m * D_DIM + q * 4);
                uint2 u = make_uint2(pack_h2(v.x, v.y), pack_h2(v.z, v.w));
                *reinterpret_cast<uint2*>(XW + m * 36 + q * 2) = u;
            }
            __syncthreads();
#pragma unroll
            for (int ks = 0; ks < 4; ks++) {
#pragma unroll
                for (int i = 0; i < 2; i++) {
                    int m = wm * 32 + i * 16 + g;
                    int k = ks * 8 + tg;
                    A[ks][i][0] = XW[m * 36 + k];
                    A[ks][i][1] = XW[(m + 8) * 36 + k];
                    A[ks][i][2] = XW[m * 36 + k + 4];
                    A[ks][i][3] = XW[(m + 8) * 36 + k + 4];
                }
            }
        }

        if (it + 2 < NIT)
            issue_b(sb, (it + 2) % 3, (it + 2) & 7, (it + 2) >> 3, nb64, h, tid);
        CP_COMMIT();

        const char* Bb = sm + BOFF + (it % 3) * 4096 + wn * 2048 + lane * 16;

        float P[2][2][4];
#pragma unroll
        for (int i = 0; i < 2; i++)
#pragma unroll
            for (int j = 0; j < 2; j++)
#pragma unroll
                for (int r = 0; r < 4; r++) P[i][j][r] = 0.f;

#pragma unroll
        for (int ks = 0; ks < 4; ks++) {
            uint4 bv = *reinterpret_cast<const uint4*>(Bb + ks * 512);
            uint32_t b[2][2];
            b[0][0] = bv.x; b[0][1] = bv.y;
            b[1][0] = bv.z; b[1][1] = bv.w;
#pragma unroll
            for (int i = 0; i < 2; i++)
#pragma unroll
                for (int j = 0; j < 2; j++)
                    mma_f16(P[i][j], A[ks][i], b[j]);
        }

        // Epilogue: O += cf[row, p] * P
#pragma unroll
        for (int i = 0; i < 2; i++) {
            int r0 = wm * 32 + i * 16 + g;
            float d0 = CF[r0 * P_N + p];
            float d1 = CF[(r0 + 8) * P_N + p];
#pragma unroll
            for (int j = 0; j < 2; j++) {
                O[i][j][0] = fmaf(d0, P[i][j][0], O[i][j][0]);
                O[i][j][1] = fmaf(d0, P[i][j][1], O[i][j][1]);
                O[i][j][2] = fmaf(d1, P[i][j][2], O[i][j][2]);
                O[i][j][3] = fmaf(d1, P[i][j][3], O[i][j][3]);
            }
        }
    }

    // Write output fragments
#pragma unroll
    for (int i = 0; i < 2; i++) {
        int r0 = m0 + wm * 32 + i * 16 + g;
#pragma unroll
        for (int j = 0; j < 2; j++) {
            int col = nb32 * 32 + wn * 16 + j * 8 + 2 * tg;
            float2 v0 = make_float2(O[i][j][0], O[i][j][1]);
            float2 v1 = make_float2(O[i][j][2], O[i][j][3]);
            *reinterpret_cast<float2*>(out + (size_t)r0 * W_DIM + col)       = v0;
            *reinterpret_cast<float2*>(out + (size_t)(r0 + 8) * W_DIM + col) = v1;
        }
    }
}

// ---------------------------------------------------------------------------
extern "C" void kernel_launch(void* const* d_in, const int* in_sizes, int n_in,
                              void* d_out, int out_size)
{
    const float* x   = (const float*)d_in[0];
    const float* ray = (const float*)d_in[1];
    const float* w_i = (const float*)d_in[2];
    const float* b_i = (const float*)d_in[3];
    const float* a_i = (const float*)d_in[4];
    const float* T   = (const float*)d_in[5];
    const int*   idx = (const int*)d_in[6];
    float* out = (float*)d_out;

    cudaFuncSetAttribute(gemm_kernel,
                         cudaFuncAttributeMaxDynamicSharedMemorySize, SMEM_BYTES);

    init_kernel<<<1, 1>>>();
    theta_kernel<<<B_ROWS / 8, 256>>>(x, ray);
    nodes_kernel<<<1, 32>>>(w_i, b_i, a_i, idx);
    ubuild_kernel<<<D_DIM, 256>>>(T);
    upermute_kernel<<<dim3(N_KT, 8), 256>>>();
    gemm_kernel<<<dim3(16, 16), 256, SMEM_BYTES>>>(x, out);
}

// round 15
// speedup vs baseline: 3.0980x; 1.0324x over previous
#include <cuda_runtime.h>
#include <cuda_fp16.h>
#include <math.h>
#include <stdint.h>

#define B_ROWS 2048
#define D_DIM  512
#define W_DIM  512
#define N_LEAF 64
#define N_NODE 63
#define P_N    8
#define K_TOT  (P_N * D_DIM)     // 4096
#define N_KT   (K_TOT / 64)      // 64 kc64 tiles
#define NIT    32                // 8 i-chunks x 4 p-pairs

// ---------------------------------------------------------------------------
// Device scratch (no cudaMalloc allowed)
// ---------------------------------------------------------------------------
__device__ float  g_theta[B_ROWS];
__device__ int    g_tmin_i, g_tmax_i;
__device__ float  g_Dn[P_N * N_LEAF];                        // d_l at nodes
__device__ __half g_Ut[(size_t)K_TOT * W_DIM];               // U row-major
__device__ __half g_Up[(size_t)(W_DIM / 64) * N_KT * 4096];  // U granules

// Chebyshev-1 nodes (P=8) on [-1,1] and barycentric weights (canonical)
__device__ __constant__ float c_tp[P_N] = {
    0.98078528f,  0.83146961f,  0.55557023f,  0.19509032f,
   -0.19509032f, -0.55557023f, -0.83146961f, -0.98078528f };
__device__ __constant__ float c_wp[P_N] = {
    0.19509032f, -0.55557023f,  0.83146961f, -0.98078528f,
    0.98078528f, -0.83146961f,  0.55557023f, -0.19509032f };

// ---------------------------------------------------------------------------
// Helpers
// ---------------------------------------------------------------------------
__device__ __forceinline__ uint32_t smem_u32(const void* p) {
    uint32_t a;
    asm("{ .reg .u64 t; cvta.to.shared.u64 t, %1; cvt.u32.u64 %0, t; }"
        : "=r"(a) : "l"(p));
    return a;
}

__device__ __forceinline__ float sigmoidf_(float z) { return 1.0f / (1.0f + expf(-z)); }

__device__ __forceinline__ void mma_f16(float c[4], const uint32_t a[4], const uint32_t b[2]) {
    asm volatile("mma.sync.aligned.m16n8k16.row.col.f32.f16.f16.f32 "
                 "{%0,%1,%2,%3}, {%4,%5,%6,%7}, {%8,%9}, {%0,%1,%2,%3};"
                 : "+f"(c[0]), "+f"(c[1]), "+f"(c[2]), "+f"(c[3])
                 : "r"(a[0]), "r"(a[1]), "r"(a[2]), "r"(a[3]), "r"(b[0]), "r"(b[1]));
}

__device__ __forceinline__ uint32_t pack_h2(float a, float b) {
    __half2 t = __floats2half2_rn(a, b);
    return *reinterpret_cast<uint32_t*>(&t);
}

#define CP_ASYNC16(dst, src) \
    asm volatile("cp.async.cg.shared.global [%0], [%1], 16;" :: "r"(dst), "l"(src))
#define CP_COMMIT() asm volatile("cp.async.commit_group;" ::: "memory")
#define CP_WAIT1()  asm volatile("cp.async.wait_group 1;" ::: "memory")

// ---------------------------------------------------------------------------
// Kernel 0: init min/max accumulators
// ---------------------------------------------------------------------------
__global__ void init_kernel() {
    g_tmin_i = 0x7f800000;
    g_tmax_i = 0;
}

// ---------------------------------------------------------------------------
// Kernel 1: theta per row (one warp per row) + global min/max
// ---------------------------------------------------------------------------
__global__ void __launch_bounds__(256) theta_kernel(
    const float* __restrict__ x, const float* __restrict__ ray)
{
    __shared__ float sray[D_DIM];
    const int tid = threadIdx.x;
    for (int i = tid; i < D_DIM; i += 256) sray[i] = ray[i];
    __syncthreads();

    const int warp = tid >> 5;
    const int lane = tid & 31;
    const int row  = blockIdx.x * 8 + warp;

    const float* xr = x + (size_t)row * D_DIM;
    float dot = 0.f, ss = 0.f, rss = 0.f;
#pragma unroll
    for (int j = 0; j < 4; j++) {
        float4 xv = reinterpret_cast<const float4*>(xr)[lane + 32 * j];
        float4 rv = reinterpret_cast<const float4*>(sray)[lane + 32 * j];
        dot += xv.x * rv.x + xv.y * rv.y + xv.z * rv.z + xv.w * rv.w;
        ss  += xv.x * xv.x + xv.y * xv.y + xv.z * xv.z + xv.w * xv.w;
        rss += rv.x * rv.x + rv.y * rv.y + rv.z * rv.z + rv.w * rv.w;
    }
#pragma unroll
    for (int o = 16; o > 0; o >>= 1) {
        dot += __shfl_xor_sync(0xffffffffu, dot, o);
        ss  += __shfl_xor_sync(0xffffffffu, ss,  o);
        rss += __shfl_xor_sync(0xffffffffu, rss, o);
    }
    float xn = fmaxf(sqrtf(ss),  1e-8f);
    float rn = fmaxf(sqrtf(rss), 1e-8f);
    float c  = dot / (xn * rn);
    c = fminf(fmaxf(c, -1.0f), 1.0f);
    const float angle = acosf(c) * 0.3183098861837907f;

    if (lane == 0) {
        g_theta[row] = angle;
        atomicMin(&g_tmin_i, __float_as_int(angle));
        atomicMax(&g_tmax_i, __float_as_int(angle));
    }
}

// ---------------------------------------------------------------------------
// Kernel 2: evaluate leaf distribution at the P_N Chebyshev nodes (exact tree)
// ---------------------------------------------------------------------------
__global__ void nodes_kernel(
    const float* __restrict__ w_i, const float* __restrict__ b_i,
    const float* __restrict__ a_i, const int* __restrict__ idx)
{
    const int p = threadIdx.x;
    if (p >= P_N) return;
    float tmin = __int_as_float(g_tmin_i);
    float tmax = __int_as_float(g_tmax_i);
    float c0 = 0.5f * (tmin + tmax);
    float hh = 0.5f * (tmax - tmin) + 1e-6f;
    float th = c0 + hh * c_tp[p];

    float dec[N_NODE];
    for (int n = 0; n < N_NODE; n++) {
        float nf = (0.5f + sigmoidf_(w_i[n])) * th - sigmoidf_(b_i[n]);
        dec[n] = sigmoidf_(nf * (1.0f + a_i[n]));
    }
    for (int l = 0; l < N_LEAF; l++) {
        float pr = 1.0f;
        for (int t = 0; t < 6; t++) {
            int j = idx[l * 6 + t];
            float v = (j < N_NODE) ? dec[j] : (1.0f - dec[j - N_NODE]);
            pr *= v;
        }
        g_Dn[p * N_LEAF + l] = pr;
    }
}

// ---------------------------------------------------------------------------
// Kernel 3: U-build.  g_Ut[p*512+i][w] = sum_l Dn[p][l]*T[l][i][w].
// Grid 512 (one i per block); 256 threads, one float2 of w each
// (acc regs halved, no smem reduction) -> high occupancy, deep MLP.
// ---------------------------------------------------------------------------
__global__ void __launch_bounds__(256, 5) ubuild_kernel(const float* __restrict__ T) {
    __shared__ float sDn[P_N * N_LEAF];
    const int tid = threadIdx.x;
    for (int e = tid; e < P_N * N_LEAF; e += 256) sDn[e] = g_Dn[e];
    __syncthreads();

    const int i = blockIdx.x;

    float acc[P_N][2];
#pragma unroll
    for (int p = 0; p < P_N; p++) { acc[p][0] = 0.f; acc[p][1] = 0.f; }

    const float* tp = T + (size_t)i * W_DIM + (size_t)tid * 2;
#pragma unroll 4
    for (int l = 0; l < N_LEAF; l++) {
        float2 t = *reinterpret_cast<const float2*>(tp + (size_t)l * D_DIM * W_DIM);
#pragma unroll
        for (int p = 0; p < P_N; p++) {
            float s = sDn[p * N_LEAF + l];
            acc[p][0] = fmaf(s, t.x, acc[p][0]);
            acc[p][1] = fmaf(s, t.y, acc[p][1]);
        }
    }
#pragma unroll
    for (int p = 0; p < P_N; p++) {
        uint32_t u = pack_h2(acc[p][0], acc[p][1]);
        *reinterpret_cast<uint32_t*>(g_Ut + ((size_t)(p * D_DIM + i)) * W_DIM + tid * 2) = u;
    }
}

// ---------------------------------------------------------------------------
// Kernel 4: permute U into B-granule tiles (per (nb64, kt): 8KB, 512 rows;
// row r=(ws*4+ks)*32+lane holds {k0,k0+1|n0},{k0+8,k0+9|n0},{..|n1},{..|n1})
// ---------------------------------------------------------------------------
__global__ void __launch_bounds__(256) upermute_kernel() {
    __shared__ unsigned short tile[64][72];   // [k][w]
    const int tid = threadIdx.x;
    const int kt = blockIdx.x;                // 0..63
    const int nb = blockIdx.y;                // 0..7
    const int k0g = kt * 64, w0 = nb * 64;

#pragma unroll
    for (int e = 0; e < 2; e++) {
        int id = tid + e * 256;
        int row = id >> 3, q = id & 7;
        uint4 v = *reinterpret_cast<const uint4*>(
            g_Ut + (size_t)(k0g + row) * W_DIM + w0 + q * 8);
        *reinterpret_cast<uint4*>(&tile[row][q * 8]) = v;
    }
    __syncthreads();

    __half* dst = g_Up + ((size_t)nb * N_KT + kt) * 4096;
#pragma unroll
    for (int t2 = 0; t2 < 2; t2++) {
        int gid = tid + t2 * 256;
        int fid = gid >> 5, ln = gid & 31;
        int ws = fid >> 2, ks = fid & 3;
        int g = ln >> 2, tg = ln & 3;
        int k0 = ks * 16 + 2 * tg;
        int n0 = ws * 16 + g, n1 = n0 + 8;
        uint4 u;
        u.x = (uint32_t)tile[k0][n0]     | ((uint32_t)tile[k0 + 1][n0] << 16);
        u.y = (uint32_t)tile[k0 + 8][n0] | ((uint32_t)tile[k0 + 9][n0] << 16);
        u.z = (uint32_t)tile[k0][n1]     | ((uint32_t)tile[k0 + 1][n1] << 16);
        u.w = (uint32_t)tile[k0 + 8][n1] | ((uint32_t)tile[k0 + 9][n1] << 16);
        *reinterpret_cast<uint4*>(dst + gid * 8) = u;
    }
}

// ---------------------------------------------------------------------------
// Kernel 5: GEMM with on-the-fly A.  out[b,w] = sum_p cf[b,p] (x_b . U_p)[w].
// CTA 128m x 32n, 256 thr = 8 warps (4m x 2n), warp tile 32m x 16n.
// NIT=32: it = ic*4 + pp; each iteration stages an 8KB B tile holding BOTH
// p = 2*pp and p = 2*pp+1 slices (one wait+sync per 32 HMMA), then runs two
// 16-HMMA + cf-epilogue sub-steps.  X fragments register-resident per chunk.
// ---------------------------------------------------------------------------
// smem: XW [128 rows][36 words] @0 (18432) | B 3x8192 @18432 | CF @43008
#define XWOFF  0
#define BOFF   18432
#define CFOFF  43008
#define SMEM_BYTES (43008 + 4096)

__device__ __forceinline__ void issue_b2(uint32_t sb, int buf, int pbase, int ic,
                                         int nb64, int h, int tid) {
    const int ws2 = tid >> 7, ks = (tid >> 5) & 3, ln = tid & 31;
    const uint32_t off_in  = ((2 * h + ws2) * 4 + ks) * 512 + ln * 16;
    const uint32_t off_out = (ws2 * 4 + ks) * 512 + ln * 16;
#pragma unroll
    for (int q = 0; q < 2; q++) {
        const char* src = (const char*)(g_Up +
            ((size_t)nb64 * N_KT + (pbase + q) * 8 + ic) * 4096) + off_in;
        uint32_t dst = sb + BOFF + buf * 8192 + q * 4096 + off_out;
        CP_ASYNC16(dst, src);
    }
}

__global__ void __launch_bounds__(256, 2) gemm_kernel(
    const float* __restrict__ x, float* __restrict__ out)
{
    extern __shared__ char sm[];
    const uint32_t sb = smem_u32(sm);
    const int tid  = threadIdx.x;
    const int wid  = tid >> 5;
    const int lane = tid & 31;
    const int wm   = wid & 3;        // 4 m-warps (32 rows each)
    const int wn   = wid >> 2;       // 2 n-warps (16 cols each)
    const int g    = lane >> 2;
    const int tg   = lane & 3;
    const int nb32 = blockIdx.x;     // 0..15
    const int nb64 = nb32 >> 1;
    const int h    = nb32 & 1;
    const int mb = blockIdx.y;       // 0..15
    const int m0 = mb * 128;

    uint32_t* XW = reinterpret_cast<uint32_t*>(sm + XWOFF);  // pitch 36 words
    float*    CF = reinterpret_cast<float*>(sm + CFOFF);     // [128][8]

    // Barycentric coefficients for this CTA's 128 rows
    if (tid < 128) {
        float tmin = __int_as_float(g_tmin_i);
        float tmax = __int_as_float(g_tmax_i);
        float c0 = 0.5f * (tmin + tmax);
        float hh = 0.5f * (tmax - tmin) + 1e-6f;
        float t = (g_theta[m0 + tid] - c0) / hh;
        float num[P_N];
        float S = 0.f;
        int hit = -1;
#pragma unroll
        for (int p = 0; p < P_N; p++) {
            float d = t - c_tp[p];
            if (fabsf(d) < 1e-7f) hit = p;
            num[p] = c_wp[p] / d;
            S += num[p];
        }
        if (hit >= 0) {
#pragma unroll
            for (int p = 0; p < P_N; p++) CF[tid * P_N + p] = (p == hit) ? 1.f : 0.f;
        } else {
            float inv = 1.f / S;
#pragma unroll
            for (int p = 0; p < P_N; p++) CF[tid * P_N + p] = num[p] * inv;
        }
    }

    float O[2][2][4];
#pragma unroll
    for (int i = 0; i < 2; i++)
#pragma unroll
        for (int j = 0; j < 2; j++)
#pragma unroll
            for (int r = 0; r < 4; r++) O[i][j][r] = 0.f;

    // Prologue: B for it=0 (ic0, p0-1) and it=1 (ic0, p2-3)
    issue_b2(sb, 0, 0, 0, nb64, h, tid);
    CP_COMMIT();
    issue_b2(sb, 1, 2, 0, nb64, h, tid);
    CP_COMMIT();

    uint32_t A[4][2][4];   // x fragments for the 64k chunk

    for (int it = 0; it < NIT; it++) {
        const int pp = it & 3;

        CP_WAIT1();
        __syncthreads();

        if (pp == 0) {
            // ---- rebuild X [128m x 64k] fp16 from x fp32 (8 times total) ----
            const float* xp = x + (size_t)m0 * D_DIM + (it >> 2) * 64;
#pragma unroll
            for (int e = 0; e < 8; e++) {
                int id = tid + e * 256;         // 0..2047 float4 (128 rows x 16)
                int m = id >> 4, q = id & 15;
                float4 v = *reinterpret_cast<const float4*>(xp + (size_t)m * D_DIM + q * 4);
                uint2 u = make_uint2(pack_h2(v.x, v.y), pack_h2(v.z, v.w));
                *reinterpret_cast<uint2*>(XW + m * 36 + q * 2) = u;
            }
            __syncthreads();
#pragma unroll
            for (int ks = 0; ks < 4; ks++) {
#pragma unroll
                for (int i = 0; i < 2; i++) {
                    int m = wm * 32 + i * 16 + g;
                    int k = ks * 8 + tg;
                    A[ks][i][0] = XW[m * 36 + k];
                    A[ks][i][1] = XW[(m + 8) * 36 + k];
                    A[ks][i][2] = XW[m * 36 + k + 4];
                    A[ks][i][3] = XW[(m + 8) * 36 + k + 4];
                }
            }
        }

        if (it + 2 < NIT)
            issue_b2(sb, (it + 2) % 3, 2 * ((it + 2) & 3), (it + 2) >> 2, nb64, h, tid);
        CP_COMMIT();

#pragma unroll
        for (int q = 0; q < 2; q++) {
            const int p = 2 * pp + q;
            const char* Bb = sm + BOFF + (it % 3) * 8192 + q * 4096
                             + wn * 2048 + lane * 16;

            float P[2][2][4];
#pragma unroll
            for (int i = 0; i < 2; i++)
#pragma unroll
                for (int j = 0; j < 2; j++)
#pragma unroll
                    for (int r = 0; r < 4; r++) P[i][j][r] = 0.f;

#pragma unroll
            for (int ks = 0; ks < 4; ks++) {
                uint4 bv = *reinterpret_cast<const uint4*>(Bb + ks * 512);
                uint32_t b[2][2];
                b[0][0] = bv.x; b[0][1] = bv.y;
                b[1][0] = bv.z; b[1][1] = bv.w;
#pragma unroll
                for (int i = 0; i < 2; i++)
#pragma unroll
                    for (int j = 0; j < 2; j++)
                        mma_f16(P[i][j], A[ks][i], b[j]);
            }

            // Epilogue: O += cf[row, p] * P
#pragma unroll
            for (int i = 0; i < 2; i++) {
                int r0 = wm * 32 + i * 16 + g;
                float d0 = CF[r0 * P_N + p];
                float d1 = CF[(r0 + 8) * P_N + p];
#pragma unroll
                for (int j = 0; j < 2; j++) {
                    O[i][j][0] = fmaf(d0, P[i][j][0], O[i][j][0]);
                    O[i][j][1] = fmaf(d0, P[i][j][1], O[i][j][1]);
                    O[i][j][2] = fmaf(d1, P[i][j][2], O[i][j][2]);
                    O[i][j][3] = fmaf(d1, P[i][j][3], O[i][j][3]);
                }
            }
        }
    }

    // Write output fragments
#pragma unroll
    for (int i = 0; i < 2; i++) {
        int r0 = m0 + wm * 32 + i * 16 + g;
#pragma unroll
        for (int j = 0; j < 2; j++) {
            int col = nb32 * 32 + wn * 16 + j * 8 + 2 * tg;
            float2 v0 = make_float2(O[i][j][0], O[i][j][1]);
            float2 v1 = make_float2(O[i][j][2], O[i][j][3]);
            *reinterpret_cast<float2*>(out + (size_t)r0 * W_DIM + col)       = v0;
            *reinterpret_cast<float2*>(out + (size_t)(r0 + 8) * W_DIM + col) = v1;
        }
    }
}

// ---------------------------------------------------------------------------
extern "C" void kernel_launch(void* const* d_in, const int* in_sizes, int n_in,
                              void* d_out, int out_size)
{
    const float* x   = (const float*)d_in[0];
    const float* ray = (const float*)d_in[1];
    const float* w_i = (const float*)d_in[2];
    const float* b_i = (const float*)d_in[3];
    const float* a_i = (const float*)d_in[4];
    const float* T   = (const float*)d_in[5];
    const int*   idx = (const int*)d_in[6];
    float* out = (float*)d_out;

    cudaFuncSetAttribute(gemm_kernel,
                         cudaFuncAttributeMaxDynamicSharedMemorySize, SMEM_BYTES);

    init_kernel<<<1, 1>>>();
    theta_kernel<<<B_ROWS / 8, 256>>>(x, ray);
    nodes_kernel<<<1, 32>>>(w_i, b_i, a_i, idx);
    ubuild_kernel<<<D_DIM, 256>>>(T);
    upermute_kernel<<<dim3(N_KT, 8), 256>>>();
    gemm_kernel<<<dim3(16, 16), 256, SMEM_BYTES>>>(x, out);
}